// round 1
// baseline (speedup 1.0000x reference)
#include <cuda_runtime.h>

#define BATCH 8
#define CIN   128
#define HT    112
#define WD    112
#define COUT  256
#define HW    (HT*WD)

#define TW 32
#define TH 16
#define CSTEP 8

// scratch (no allocations allowed in kernel_launch)
__device__ float g_csum[BATCH*HW];
__device__ float g_inv[BATCH*HW];

// ---------------------------------------------------------------------------
// Kernel 1: per-pixel channel sum of squares
// ---------------------------------------------------------------------------
__global__ void csum_kernel(const float* __restrict__ x) {
    int idx = blockIdx.x * 256 + threadIdx.x;
    if (idx >= BATCH*HW) return;
    int b = idx / HW;
    int p = idx - b*HW;
    const float* xp = x + (size_t)b*CIN*HW + p;
    float s = 0.f;
#pragma unroll 8
    for (int c = 0; c < CIN; ++c) {
        float v = xp[c*HW];
        s += v * v;
    }
    g_csum[idx] = s;
}

// ---------------------------------------------------------------------------
// Kernel 2: 3x3 box sum (zero pad) -> 1/max(sqrt(s), eps)
// ---------------------------------------------------------------------------
__global__ void inv_kernel() {
    int idx = blockIdx.x * 256 + threadIdx.x;
    if (idx >= BATCH*HW) return;
    int b = idx / HW;
    int p = idx - b*HW;
    int oy = p / WD, ox = p - oy*WD;
    float s = 0.f;
#pragma unroll
    for (int dy = -1; dy <= 1; ++dy) {
        int y = oy + dy;
        if ((unsigned)y >= HT) continue;
#pragma unroll
        for (int dx = -1; dx <= 1; ++dx) {
            int xq = ox + dx;
            if ((unsigned)xq >= WD) continue;
            s += g_csum[b*HW + y*WD + xq];
        }
    }
    g_inv[idx] = 1.f / fmaxf(sqrtf(s), 1e-12f);
}

// ---------------------------------------------------------------------------
// Packed f32x2 helpers (Blackwell FFMA2 — only reachable via PTX)
// ---------------------------------------------------------------------------
__device__ __forceinline__ unsigned long long dup_f32x2(float v) {
    unsigned long long r;
    unsigned u = __float_as_uint(v);
    asm("mov.b64 %0, {%1, %2};" : "=l"(r) : "r"(u), "r"(u));
    return r;
}
__device__ __forceinline__ void fma2(unsigned long long& d,
                                     unsigned long long a,
                                     unsigned long long b) {
    asm("fma.rn.f32x2 %0, %1, %2, %0;" : "+l"(d) : "l"(a), "l"(b));
}
__device__ __forceinline__ void unpack_f32x2(unsigned long long v, float& lo, float& hi) {
    unsigned ulo, uhi;
    asm("mov.b64 {%0, %1}, %2;" : "=r"(ulo), "=r"(uhi) : "l"(v));
    lo = __uint_as_float(ulo);
    hi = __uint_as_float(uhi);
}

// ---------------------------------------------------------------------------
// Kernel 3: tiled direct 3x3 conv, fused scale + bias epilogue.
// Block 32x8, output tile 32x16 pixels x 8 couts.
// Each thread: 2 pixels (ty, ty+8) x 8 couts = 4 f32x2 accumulators/pixel
// (couts paired so the smem float4 weight load is directly the packed mult).
// ---------------------------------------------------------------------------
__global__ __launch_bounds__(256)
void conv_kernel(const float* __restrict__ x,
                 const float* __restrict__ wgt,
                 const float* __restrict__ bias,
                 float* __restrict__ out) {
    __shared__ __align__(16) float sx[CSTEP][TH+2][TW+2];
    __shared__ __align__(16) float sw[CSTEP][9][8];

    const int tx  = threadIdx.x;
    const int ty  = threadIdx.y;
    const int tid = ty * 32 + tx;
    const int x0  = blockIdx.x * TW;
    const int y0  = blockIdx.y * TH;
    const int b   = blockIdx.z >> 5;
    const int co0 = (blockIdx.z & 31) * 8;

    unsigned long long acc[2][4];
#pragma unroll
    for (int i = 0; i < 2; ++i)
#pragma unroll
        for (int j = 0; j < 4; ++j) acc[i][j] = 0ull;

    const float* xb = x + (size_t)b * CIN * HW;

    for (int ci0 = 0; ci0 < CIN; ci0 += CSTEP) {
        __syncthreads();
        // ---- stage x tile (with halo, zero-padded) ----
        const int XT = (TH+2) * (TW+2);   // 612
        for (int i = tid; i < CSTEP * XT; i += 256) {
            int cin = i / XT;
            int r   = i - cin * XT;
            int ly  = r / (TW+2);
            int lx  = r - ly * (TW+2);
            int gy  = y0 - 1 + ly;
            int gx  = x0 - 1 + lx;
            float v = 0.f;
            if ((unsigned)gy < HT && (unsigned)gx < WD)
                v = xb[(ci0 + cin) * HW + gy * WD + gx];
            sx[cin][ly][lx] = v;
        }
        // ---- stage weights: layout [cin][k][co] (co fastest) ----
        for (int i = tid; i < CSTEP * 9 * 8; i += 256) {
            int co  = i & 7;
            int r   = i >> 3;
            int k   = r % 9;
            int cin = r / 9;
            sw[cin][k][co] = wgt[((size_t)(co0 + co) * CIN + ci0 + cin) * 9 + k];
        }
        __syncthreads();

        // ---- compute ----
#pragma unroll
        for (int cin = 0; cin < CSTEP; ++cin) {
#pragma unroll
            for (int kh = 0; kh < 3; ++kh) {
#pragma unroll
                for (int kw = 0; kw < 3; ++kw) {
                    float xv0 = sx[cin][ty + kh][tx + kw];
                    float xv1 = sx[cin][ty + 8 + kh][tx + kw];
                    unsigned long long xd0 = dup_f32x2(xv0);
                    unsigned long long xd1 = dup_f32x2(xv1);
                    const int k = kh * 3 + kw;
                    ulonglong2 wA = *(const ulonglong2*)&sw[cin][k][0];
                    ulonglong2 wB = *(const ulonglong2*)&sw[cin][k][4];
                    fma2(acc[0][0], wA.x, xd0);
                    fma2(acc[0][1], wA.y, xd0);
                    fma2(acc[0][2], wB.x, xd0);
                    fma2(acc[0][3], wB.y, xd0);
                    fma2(acc[1][0], wA.x, xd1);
                    fma2(acc[1][1], wA.y, xd1);
                    fma2(acc[1][2], wB.x, xd1);
                    fma2(acc[1][3], wB.y, xd1);
                }
            }
        }
    }

    // ---- epilogue: scale by inv_norm, add bias ----
    const int px = x0 + tx;
    if (px < WD) {
        float bv[8];
#pragma unroll
        for (int co = 0; co < 8; ++co) bv[co] = bias[co0 + co];
#pragma unroll
        for (int pi = 0; pi < 2; ++pi) {
            int py = y0 + ty + pi * 8;
            float scale = g_inv[b * HW + py * WD + px];
#pragma unroll
            for (int cp = 0; cp < 4; ++cp) {
                float lo, hi;
                unpack_f32x2(acc[pi][cp], lo, hi);
                int co = cp * 2;
                size_t o0 = ((size_t)b * COUT + co0 + co) * HW + py * WD + px;
                out[o0]      = lo * scale + bv[co];
                out[o0 + HW] = hi * scale + bv[co + 1];
            }
        }
    }
}

// ---------------------------------------------------------------------------
extern "C" void kernel_launch(void* const* d_in, const int* in_sizes, int n_in,
                              void* d_out, int out_size) {
    const float* x    = (const float*)d_in[0];
    const float* wgt  = (const float*)d_in[1];
    const float* bias = (const float*)d_in[2];
    float* out        = (float*)d_out;

    int npix = BATCH * HW;
    csum_kernel<<<(npix + 255) / 256, 256>>>(x);
    inv_kernel<<<(npix + 255) / 256, 256>>>();

    dim3 grid((WD + TW - 1) / TW, HT / TH, BATCH * (COUT / 8));  // (4, 7, 256)
    dim3 block(32, 8);
    conv_kernel<<<grid, block>>>(x, wgt, bias, out);
}

// round 3
// speedup vs baseline: 3.6747x; 3.6747x over previous
#include <cuda_runtime.h>
#include <cstdint>
#include <cstddef>

#define BATCH 8
#define CIN   128
#define HT    112
#define WD    112
#define COUT  256
#define HW    (HT*WD)

#define NT    224          // pixels per CTA tile (2 rows)
#define MT    128          // couts per CTA tile
#define WIN   456          // staged window pitch (450 valid + pad, mod32==8)
#define PA    136          // A tile pitch (words), mod32==8
#define PC    228          // epilogue pitch

#define W_OFF   0
#define W_BYTES (32*WIN*4)          // 58368
#define A_OFF   58368
#define A_SZ    (32*PA*4)           // 17408
#define SINV_OFF 116736             // == 128*PC*4 (c_s size)
#define DSMEM   117760

__device__ float g_csum[BATCH*HW];
__device__ float g_inv [BATCH*HW];
__device__ float g_w2  [9*CIN*COUT];   // [pos][ci][co], tf32-pre-rounded

// ---------------------------------------------------------------------------
__device__ __forceinline__ uint32_t smem_u32(const void* p) {
    uint32_t a;
    asm("{ .reg .u64 t; cvta.to.shared.u64 t, %1; cvt.u32.u64 %0, t; }" : "=r"(a) : "l"(p));
    return a;
}
__device__ __forceinline__ uint32_t cvt_tf32(float f) {
    uint32_t r; asm("cvt.rna.tf32.f32 %0, %1;" : "=r"(r) : "f"(f)); return r;
}
__device__ __forceinline__ void cpa4(uint32_t d, const void* s, unsigned sz) {
    asm volatile("cp.async.ca.shared.global [%0], [%1], 4, %2;" :: "r"(d), "l"(s), "r"(sz));
}
__device__ __forceinline__ void cpa16(uint32_t d, const void* s) {
    asm volatile("cp.async.cg.shared.global [%0], [%1], 16;" :: "r"(d), "l"(s));
}
#define CP_COMMIT() asm volatile("cp.async.commit_group;" ::: "memory")
#define CP_WAIT(n)  asm volatile("cp.async.wait_group %0;" :: "n"(n) : "memory")

__device__ __forceinline__ void mma8(float* c, const uint32_t* a, uint32_t b0, uint32_t b1) {
    asm volatile(
        "mma.sync.aligned.m16n8k8.row.col.f32.tf32.tf32.f32 "
        "{%0,%1,%2,%3}, {%4,%5,%6,%7}, {%8,%9}, {%0,%1,%2,%3};"
        : "+f"(c[0]), "+f"(c[1]), "+f"(c[2]), "+f"(c[3])
        : "r"(a[0]), "r"(a[1]), "r"(a[2]), "r"(a[3]), "r"(b0), "r"(b1));
}

// ---------------------------------------------------------------------------
// Pre-kernels
// ---------------------------------------------------------------------------
__global__ void csum_kernel(const float* __restrict__ x) {
    int idx = blockIdx.x * 256 + threadIdx.x;
    if (idx >= BATCH*HW) return;
    int b = idx / HW, p = idx - b*HW;
    const float* xp = x + (size_t)b*CIN*HW + p;
    float s = 0.f;
#pragma unroll 8
    for (int c = 0; c < CIN; ++c) { float v = xp[c*HW]; s += v*v; }
    g_csum[idx] = s;
}

__global__ void inv_kernel() {
    int idx = blockIdx.x * 256 + threadIdx.x;
    if (idx >= BATCH*HW) return;
    int b = idx / HW, p = idx - b*HW;
    int oy = p / WD, ox = p - oy*WD;
    float s = 0.f;
#pragma unroll
    for (int dy = -1; dy <= 1; ++dy) {
        int y = oy + dy; if ((unsigned)y >= HT) continue;
#pragma unroll
        for (int dx = -1; dx <= 1; ++dx) {
            int xq = ox + dx; if ((unsigned)xq >= WD) continue;
            s += g_csum[b*HW + y*WD + xq];
        }
    }
    g_inv[idx] = 1.f / fmaxf(sqrtf(s), 1e-12f);
}

__global__ void wtrans_kernel(const float* __restrict__ w) {
    int idx = blockIdx.x * 256 + threadIdx.x;
    if (idx >= 9*CIN*COUT) return;
    int co = idx & 255;
    int r  = idx >> 8;
    int ci = r & 127;
    int pos = r >> 7;
    g_w2[idx] = __uint_as_float(cvt_tf32(w[((size_t)co*CIN + ci)*9 + pos]));
}

// ---------------------------------------------------------------------------
// Main conv GEMM: grid (56 px-tiles, 2 cout-tiles, 8 batch), 512 threads.
// ---------------------------------------------------------------------------
__global__ __launch_bounds__(512, 1)
void conv_mma_kernel(const float* __restrict__ x,
                     const float* __restrict__ bias,
                     float* __restrict__ out) {
    extern __shared__ __align__(16) char dyn[];
    float* w_sf   = (float*)(dyn + W_OFF);
    float* sInvF  = (float*)(dyn + SINV_OFF);
    const uint32_t sbase = smem_u32(dyn);

    const int tid  = threadIdx.x;
    const int wid  = tid >> 5;
    const int lane = tid & 31;
    const int t    = lane & 3;
    const int g    = lane >> 2;
    const int m0w  = (wid & 3) * 32;
    const int n0w  = (wid >> 2) * 56;

    const int p0  = blockIdx.x * NT;
    const int co0 = blockIdx.y * MT;
    const int b   = blockIdx.z;
    const float* xb = x + (size_t)b * CIN * HW;

    if (tid < NT) sInvF[tid] = g_inv[b * HW + p0 + tid];

    float acc[2][7][4];
#pragma unroll
    for (int mi = 0; mi < 2; ++mi)
#pragma unroll
        for (int ni = 0; ni < 7; ++ni)
#pragma unroll
            for (int q = 0; q < 4; ++q) acc[mi][ni][q] = 0.f;

    // --- stagers ---
    auto issueB = [&](int chunk) {
        const int ci0 = chunk * 32;
#pragma unroll 4
        for (int i = 0; i < 29; ++i) {
            int idx = i * 512 + tid;
            if (idx < 32 * WIN) {
                int ci = idx / WIN;
                int j  = idx - ci * WIN;
                int q  = p0 - 113 + j;
                unsigned ok = ((unsigned)q < (unsigned)HW) ? 4u : 0u;
                int qc = q < 0 ? 0 : (q >= HW ? HW - 1 : q);
                cpa4(sbase + W_OFF + (uint32_t)idx * 4,
                     xb + (size_t)(ci0 + ci) * HW + qc, ok);
            }
        }
    };
    auto issueA = [&](int it2) {
        const int pos2 = it2 % 9, chunk2 = it2 / 9;
        const int ci0 = chunk2 * 32;
        const uint32_t aB = sbase + A_OFF + (uint32_t)(it2 & 1) * A_SZ;
#pragma unroll
        for (int e = 0; e < 2; ++e) {
            int f  = e * 512 + tid;
            int ci = f >> 5;
            int c4 = (f & 31) << 2;
            cpa16(aB + (uint32_t)(ci * PA + c4) * 4,
                  g_w2 + ((size_t)(pos2 * CIN + ci0 + ci)) * COUT + co0 + c4);
        }
    };

    for (int it = 0; it < 36; ++it) {
        const int pos = it % 9;
        const int kh = pos / 3, kw = pos - kh * 3;
        const int dlt = (kh - 1) * WD + (kw - 1) + 113;

        if (pos == 0) { issueB(it / 9); issueA(it); CP_COMMIT(); }
        if (pos < 8)  { issueA(it + 1); CP_COMMIT(); }
        if (pos < 8)  { CP_WAIT(1); } else { CP_WAIT(0); }
        __syncthreads();

        const float* a_sf = (const float*)(dyn + A_OFF + (it & 1) * A_SZ);
#pragma unroll
        for (int ks = 0; ks < 4; ++ks) {
            const int k0 = ks * 8;
            uint32_t A[2][4];
#pragma unroll
            for (int mi = 0; mi < 2; ++mi) {
                const int m = m0w + mi * 16 + g;
                A[mi][0] = __float_as_uint(a_sf[(k0 + t)     * PA + m]);
                A[mi][1] = __float_as_uint(a_sf[(k0 + t)     * PA + m + 8]);
                A[mi][2] = __float_as_uint(a_sf[(k0 + t + 4) * PA + m]);
                A[mi][3] = __float_as_uint(a_sf[(k0 + t + 4) * PA + m + 8]);
            }
#pragma unroll
            for (int ni = 0; ni < 7; ++ni) {
                const int j = n0w + ni * 8 + g + dlt;
                uint32_t B0 = cvt_tf32(w_sf[(k0 + t)     * WIN + j]);
                uint32_t B1 = cvt_tf32(w_sf[(k0 + t + 4) * WIN + j]);
                mma8(acc[0][ni], A[0], B0, B1);
                mma8(acc[1][ni], A[1], B0, B1);
            }
        }
        __syncthreads();
    }

    // --- epilogue: accum -> smem -> scaled, biased, coalesced STG ---
    float* c_s = (float*)dyn;
#pragma unroll
    for (int mi = 0; mi < 2; ++mi)
#pragma unroll
        for (int ni = 0; ni < 7; ++ni) {
            const int m = m0w + mi * 16 + g;
            const int n = n0w + ni * 8 + 2 * t;
            c_s[m * PC + n]           = acc[mi][ni][0];
            c_s[m * PC + n + 1]       = acc[mi][ni][1];
            c_s[(m + 8) * PC + n]     = acc[mi][ni][2];
            c_s[(m + 8) * PC + n + 1] = acc[mi][ni][3];
        }
    __syncthreads();

    {
        const int m  = tid >> 2;
        const int cb = (tid & 3) * 56;
        const float bv = bias[co0 + m];
        float* op = out + ((size_t)b * COUT + co0 + m) * HW + p0 + cb;
#pragma unroll
        for (int j4 = 0; j4 < 14; ++j4) {
            float4 v = *(const float4*)&c_s[m * PC + cb + j4 * 4];
            float4 r;
            r.x = v.x * sInvF[cb + j4 * 4 + 0] + bv;
            r.y = v.y * sInvF[cb + j4 * 4 + 1] + bv;
            r.z = v.z * sInvF[cb + j4 * 4 + 2] + bv;
            r.w = v.w * sInvF[cb + j4 * 4 + 3] + bv;
            *(float4*)&op[j4 * 4] = r;
        }
    }
}

// ---------------------------------------------------------------------------
// Edge fixup: subtract the row-wrap garbage included at ox==0 (kw=0) and
// ox==111 (kw=2). grid (7 oy-chunks, 8 b, 2 sides), 256 threads (one co each).
// ---------------------------------------------------------------------------
__global__ void fixup_kernel(const float* __restrict__ x,
                             float* __restrict__ out) {
    const int side = blockIdx.z;       // 0 = left (ox=0), 1 = right (ox=111)
    const int b    = blockIdx.y;
    const int oc   = blockIdx.x * 16;
    const int co   = threadIdx.x;

    __shared__ float xc[128][18];
    for (int i = threadIdx.x; i < 128 * 18; i += 256) {
        int ci = i / 18, r = i - (i / 18) * 18;
        float v = 0.f;
        if (side == 0) {
            int row = oc - 1 + r;                       // = oy+kh-1
            if (row >= 1 && row <= HT)
                v = x[((size_t)b * CIN + ci) * HW + row * WD - 1];
        } else {
            int row = oc + r;                           // = oy+kh
            if (row <= HT - 1)
                v = x[((size_t)b * CIN + ci) * HW + row * WD];
        }
        xc[ci][r] = v;
    }
    __syncthreads();

    const int kwsel = side ? 2 : 0;
    float corr[16];
#pragma unroll
    for (int dy = 0; dy < 16; ++dy) corr[dy] = 0.f;

#pragma unroll
    for (int kh = 0; kh < 3; ++kh) {
        const float* wp = g_w2 + (size_t)((kh * 3 + kwsel) * CIN) * COUT + co;
        for (int ci = 0; ci < CIN; ++ci) {
            float w = wp[(size_t)ci * COUT];
#pragma unroll
            for (int dy = 0; dy < 16; ++dy) corr[dy] += w * xc[ci][dy + kh];
        }
    }

    const int edge = side ? (WD - 1) : 0;
#pragma unroll
    for (int dy = 0; dy < 16; ++dy) {
        int oy = oc + dy;
        float inv = g_inv[b * HW + oy * WD + edge];
        size_t o = ((size_t)b * COUT + co) * HW + (size_t)oy * WD + edge;
        out[o] -= corr[dy] * inv;
    }
}

// ---------------------------------------------------------------------------
extern "C" void kernel_launch(void* const* d_in, const int* in_sizes, int n_in,
                              void* d_out, int out_size) {
    const float* x    = (const float*)d_in[0];
    const float* wgt  = (const float*)d_in[1];
    const float* bias = (const float*)d_in[2];
    float* out        = (float*)d_out;

    cudaFuncSetAttribute(conv_mma_kernel,
                         cudaFuncAttributeMaxDynamicSharedMemorySize, DSMEM);

    int npix = BATCH * HW;
    csum_kernel<<<(npix + 255) / 256, 256>>>(x);
    inv_kernel<<<(npix + 255) / 256, 256>>>();
    wtrans_kernel<<<(9 * CIN * COUT + 255) / 256, 256>>>(wgt);

    conv_mma_kernel<<<dim3(56, 2, 8), 512, DSMEM>>>(x, bias, out);
    fixup_kernel<<<dim3(7, 8, 2), 256>>>(x, out);
}

// round 7
// speedup vs baseline: 4.9717x; 1.3530x over previous
#include <cuda_runtime.h>
#include <cuda_fp16.h>
#include <cstdint>
#include <cstddef>

#define BATCH 8
#define CIN   128
#define HT    112
#define WD    112
#define COUT  256
#define HW    (HT*WD)

#define NT    224          // pixels per CTA (2 rows)
#define MT    128          // couts per CTA
#define WROWS 450          // staged window rows (j = 0..449)
#define WPB   80           // bytes per window/A row (32 halves + pad -> 2-phase LDS.64)
#define WBUF  36096        // one window buffer (450*80 rounded to 128)
#define ABUF  10240        // one A buffer (128*80)
#define AOFF  72192        // A buffers after two window buffers
#define PC    228          // epilogue fp32 pitch
#define SINV_OFF 116736    // after c_s (128*228*4)
#define DSMEM 117632

__device__ float g_csum[BATCH*HW];
__device__ float g_inv [BATCH*HW];
__device__ __align__(256) __half g_xt[(size_t)BATCH*HW*CIN]; // [b][p][ci_perm] half
__device__ __align__(256) __half g_wh[9*COUT*CIN];           // [pos][co][ci_perm] half

// permutation of k within a 16-group so mma fragment pairs are contiguous:
// stored[pos(k)] = val[k]; pos(k) = ((k&7)>>1)*4 + ((k>>3)<<1) + (k&1)
__device__ __host__ __forceinline__ constexpr int permpos(int k) {
    return ((k & 7) >> 1) * 4 + ((k >> 3) << 1) + (k & 1);
}

// ---------------------------------------------------------------------------
__device__ __forceinline__ uint32_t smem_u32(const void* p) {
    uint32_t a;
    asm("{ .reg .u64 t; cvta.to.shared.u64 t, %1; cvt.u32.u64 %0, t; }" : "=r"(a) : "l"(p));
    return a;
}
#define CP_COMMIT() asm volatile("cp.async.commit_group;" ::: "memory")
#define CP_WAIT(n)  asm volatile("cp.async.wait_group %0;" :: "n"(n) : "memory")

__device__ __forceinline__ void lds64(uint32_t& x, uint32_t& y, uint32_t a) {
    asm volatile("ld.shared.v2.b32 {%0,%1}, [%2];" : "=r"(x), "=r"(y) : "r"(a));
}
__device__ __forceinline__ void mma16(float* c, uint32_t a0, uint32_t a1,
                                      uint32_t a2, uint32_t a3,
                                      uint32_t b0, uint32_t b1) {
    asm volatile(
        "mma.sync.aligned.m16n8k16.row.col.f32.f16.f16.f32 "
        "{%0,%1,%2,%3}, {%4,%5,%6,%7}, {%8,%9}, {%0,%1,%2,%3};"
        : "+f"(c[0]), "+f"(c[1]), "+f"(c[2]), "+f"(c[3])
        : "r"(a0), "r"(a1), "r"(a2), "r"(a3), "r"(b0), "r"(b1));
}

// ---------------------------------------------------------------------------
// prep_x: fused channel sum-of-squares (fp32, exact) + transpose x to
// [b][p][ci_perm] in half.
// ---------------------------------------------------------------------------
__global__ void prep_x(const float* __restrict__ x) {
    int idx = blockIdx.x * 256 + threadIdx.x;
    if (idx >= BATCH*HW) return;
    int b = idx / HW, p = idx - b*HW;
    const float* xp = x + (size_t)b*CIN*HW + p;
    float s = 0.f;
    __half hh[128];
#pragma unroll
    for (int gq = 0; gq < 8; ++gq)
#pragma unroll
        for (int k = 0; k < 16; ++k) {
            float v = xp[(gq*16 + k) * HW];
            s += v * v;
            hh[gq*16 + permpos(k)] = __float2half_rn(v);
        }
    g_csum[idx] = s;
    uint4* dst = (uint4*)(g_xt + (size_t)idx * 128);
    const uint4* srcv = (const uint4*)hh;
#pragma unroll
    for (int i = 0; i < 16; ++i) dst[i] = srcv[i];
}

__global__ void inv_kernel() {
    int idx = blockIdx.x * 256 + threadIdx.x;
    if (idx >= BATCH*HW) return;
    int b = idx / HW, p = idx - b*HW;
    int oy = p / WD, ox = p - oy*WD;
    float s = 0.f;
#pragma unroll
    for (int dy = -1; dy <= 1; ++dy) {
        int y = oy + dy; if ((unsigned)y >= HT) continue;
#pragma unroll
        for (int dx = -1; dx <= 1; ++dx) {
            int xq = ox + dx; if ((unsigned)xq >= WD) continue;
            s += g_csum[b*HW + y*WD + xq];
        }
    }
    g_inv[idx] = 1.f / fmaxf(sqrtf(s), 1e-12f);
}

__global__ void wtrans_kernel(const float* __restrict__ w) {
    int idx = blockIdx.x * 256 + threadIdx.x;
    if (idx >= 9*CIN*COUT) return;
    int ci  = idx & 127;
    int r   = idx >> 7;
    int co  = r & 255;
    int pos = r >> 8;
    int pc  = (ci & ~15) | permpos(ci & 15);
    g_wh[((size_t)pos*COUT + co)*CIN + pc] =
        __float2half_rn(w[((size_t)co*CIN + ci)*9 + pos]);
}

// ---------------------------------------------------------------------------
// Main conv GEMM: grid (56 px-tiles, 2 cout-tiles, 8 batch), 512 threads.
// fp16 m16n8k16 mma.sync; flat shifted-window B (9 taps = address offsets);
// double-buffered window + A via cp.async.
// ---------------------------------------------------------------------------
__global__ __launch_bounds__(512, 1)
void conv_mma_kernel(const float* __restrict__ bias, float* __restrict__ out) {
    extern __shared__ __align__(16) char dyn[];
    const uint32_t sbase = smem_u32(dyn);
    float* sInvF = (float*)(dyn + SINV_OFF);

    const int tid  = threadIdx.x;
    const int wid  = tid >> 5;
    const int lane = tid & 31;
    const int t    = lane & 3;
    const int g    = lane >> 2;
    const int m0w  = (wid & 3) * 32;
    const int n0w  = (wid >> 2) * 56;

    const int p0  = blockIdx.x * NT;
    const int co0 = blockIdx.y * MT;
    const int b   = blockIdx.z;
    const __half* xtb = g_xt + (size_t)b * HW * 128;

    if (tid < NT) sInvF[tid] = g_inv[b * HW + p0 + tid];

    float acc[2][7][4];
#pragma unroll
    for (int mi = 0; mi < 2; ++mi)
#pragma unroll
        for (int ni = 0; ni < 7; ++ni)
#pragma unroll
            for (int q = 0; q < 4; ++q) acc[mi][ni][q] = 0.f;

    auto issueW = [&](int cig) {
        uint32_t wB = sbase + (uint32_t)(cig & 1) * WBUF;
        for (int i = tid; i < WROWS * 4; i += 512) {
            int j = i >> 2, seg = i & 3;
            int q = p0 - 113 + j;
            unsigned ok = ((unsigned)q < (unsigned)HW) ? 16u : 0u;
            int qc = q < 0 ? 0 : (q >= HW ? HW - 1 : q);
            const __half* src = xtb + (size_t)qc * 128 + cig * 32 + seg * 8;
            asm volatile("cp.async.cg.shared.global [%0], [%1], 16, %2;"
                         :: "r"(wB + (uint32_t)(j * WPB + seg * 16)), "l"(src), "r"(ok));
        }
    };
    auto issueA = [&](int it2) {
        int pos = it2 % 9, cig = it2 / 9;
        uint32_t aB = sbase + AOFF + (uint32_t)(it2 & 1) * ABUF;
        int row = tid >> 2, seg = tid & 3;
        const __half* src = g_wh + ((size_t)pos*COUT + co0 + row)*CIN + cig*32 + seg*8;
        asm volatile("cp.async.cg.shared.global [%0], [%1], 16;"
                     :: "r"(aB + (uint32_t)(row * WPB + seg * 16)), "l"(src));
    };

    issueW(0); issueA(0); CP_COMMIT();

    for (int it = 0; it < 36; ++it) {
        const int tap = it % 9, cig = it / 9;
        if (it < 35) issueA(it + 1);
        if (tap == 4 && cig < 3) issueW(cig + 1);
        CP_COMMIT();
        CP_WAIT(1);
        __syncthreads();

        const int kh = tap / 3, kw = tap - kh * 3;
        const int dlt = (kh - 1) * WD + (kw - 1) + 113;
        const uint32_t aB = sbase + AOFF + (uint32_t)(it & 1) * ABUF;
        const uint32_t wB = sbase + (uint32_t)(cig & 1) * WBUF;
        const uint32_t abase = aB + (uint32_t)((m0w + g) * WPB + t * 8);
        const uint32_t bbase = wB + (uint32_t)((n0w + g + dlt) * WPB + t * 8);

#pragma unroll
        for (int ks = 0; ks < 2; ++ks) {
            uint32_t a[2][4];
#pragma unroll
            for (int mi = 0; mi < 2; ++mi) {
                lds64(a[mi][0], a[mi][2], abase + mi * 1280 + ks * 32);
                lds64(a[mi][1], a[mi][3], abase + mi * 1280 + 640 + ks * 32);
            }
#pragma unroll
            for (int ni = 0; ni < 7; ++ni) {
                uint32_t b0, b1;
                lds64(b0, b1, bbase + ni * 640 + ks * 32);
                mma16(acc[0][ni], a[0][0], a[0][1], a[0][2], a[0][3], b0, b1);
                mma16(acc[1][ni], a[1][0], a[1][1], a[1][2], a[1][3], b0, b1);
            }
        }
        __syncthreads();
    }

    // --- epilogue: accum -> smem -> scaled, biased, coalesced STG ---
    float* c_s = (float*)dyn;
#pragma unroll
    for (int mi = 0; mi < 2; ++mi)
#pragma unroll
        for (int ni = 0; ni < 7; ++ni) {
            const int m = m0w + mi * 16 + g;
            const int n = n0w + ni * 8 + 2 * t;
            c_s[m * PC + n]           = acc[mi][ni][0];
            c_s[m * PC + n + 1]       = acc[mi][ni][1];
            c_s[(m + 8) * PC + n]     = acc[mi][ni][2];
            c_s[(m + 8) * PC + n + 1] = acc[mi][ni][3];
        }
    __syncthreads();

    {
        const int m  = tid >> 2;
        const int cb = (tid & 3) * 56;
        const float bv = bias[co0 + m];
        float* op = out + ((size_t)b * COUT + co0 + m) * HW + p0 + cb;
#pragma unroll
        for (int j4 = 0; j4 < 14; ++j4) {
            float4 v = *(const float4*)&c_s[m * PC + cb + j4 * 4];
            float4 r;
            r.x = v.x * sInvF[cb + j4 * 4 + 0] + bv;
            r.y = v.y * sInvF[cb + j4 * 4 + 1] + bv;
            r.z = v.z * sInvF[cb + j4 * 4 + 2] + bv;
            r.w = v.w * sInvF[cb + j4 * 4 + 3] + bv;
            *(float4*)&op[j4 * 4] = r;
        }
    }
}

// ---------------------------------------------------------------------------
// Edge fixup: subtract the row-wrap garbage at ox==0 (kw=0) / ox==111 (kw=2).
// Uses the SAME half-rounded w and x values as the main kernel (products in
// fp32 are exact), so no precision mismatch at edges.
// ---------------------------------------------------------------------------
__global__ void fixup_kernel(float* __restrict__ out) {
    const int side = blockIdx.z;       // 0 = left (ox=0), 1 = right (ox=111)
    const int b    = blockIdx.y;
    const int oc   = blockIdx.x * 16;
    const int co   = threadIdx.x;

    __shared__ __half xc[18][128];
    for (int i = threadIdx.x; i < 18 * 16; i += 256) {
        int r = i >> 4, seg = i & 15;
        int q = 0; bool v;
        if (side == 0) { int row = oc - 1 + r; v = (row >= 1 && row <= HT); q = row * WD - 1; }
        else           { int row = oc + r;     v = (row <= HT - 1);         q = row * WD;     }
        uint4 val = make_uint4(0, 0, 0, 0);
        if (v) val = *(const uint4*)(g_xt + ((size_t)b * HW + q) * 128 + seg * 8);
        *(uint4*)&xc[r][seg * 8] = val;
    }
    __syncthreads();

    const int kwsel = side ? 2 : 0;
    float corr[16];
#pragma unroll
    for (int dy = 0; dy < 16; ++dy) corr[dy] = 0.f;

#pragma unroll
    for (int kh = 0; kh < 3; ++kh) {
        const __half* wrow = g_wh + ((size_t)(kh * 3 + kwsel) * COUT + co) * CIN;
        for (int ci = 0; ci < CIN; ++ci) {
            float w = __half2float(wrow[ci]);
#pragma unroll
            for (int dy = 0; dy < 16; ++dy)
                corr[dy] += w * __half2float(xc[dy + kh][ci]);
        }
    }

    const int edge = side ? (WD - 1) : 0;
#pragma unroll
    for (int dy = 0; dy < 16; ++dy) {
        int oy = oc + dy;
        float inv = g_inv[b * HW + oy * WD + edge];
        size_t o = ((size_t)b * COUT + co) * HW + (size_t)oy * WD + edge;
        out[o] -= corr[dy] * inv;
    }
}

// ---------------------------------------------------------------------------
extern "C" void kernel_launch(void* const* d_in, const int* in_sizes, int n_in,
                              void* d_out, int out_size) {
    const float* x    = (const float*)d_in[0];
    const float* wgt  = (const float*)d_in[1];
    const float* bias = (const float*)d_in[2];
    float* out        = (float*)d_out;

    cudaFuncSetAttribute(conv_mma_kernel,
                         cudaFuncAttributeMaxDynamicSharedMemorySize, DSMEM);

    int npix = BATCH * HW;
    prep_x<<<(npix + 255) / 256, 256>>>(x);
    inv_kernel<<<(npix + 255) / 256, 256>>>();
    wtrans_kernel<<<(9 * CIN * COUT + 255) / 256, 256>>>(wgt);

    conv_mma_kernel<<<dim3(56, 2, 8), 512, DSMEM>>>(bias, out);
    fixup_kernel<<<dim3(7, 8, 2), 256>>>(out);
}

// round 8
// speedup vs baseline: 5.9302x; 1.1928x over previous
#include <cuda_runtime.h>
#include <cuda_fp16.h>
#include <cstdint>
#include <cstddef>

#define BATCH 8
#define CIN   128
#define HT    112
#define WD    112
#define COUT  256
#define HW    (HT*WD)

#define NT    224          // pixels per CTA (2 rows)
#define MT    128          // couts per CTA
#define WROWS 450          // staged window rows
#define RPB   64           // bytes per row (32 halves, no pad; conflict-free for LDS.128)
#define WBUF  (WROWS*RPB)  // 28800
#define A_SZ  (MT*RPB)     // 8192
#define AOFF  (2*WBUF)     // 57600 (A triple buffer after two window buffers)
#define PC    228          // epilogue fp32 pitch
#define SINV_OFF 116736    // after c_s (128*228*4)
#define DSMEM 117632

__device__ float g_csum[BATCH*HW];
__device__ float g_inv [BATCH*HW];
__device__ __align__(256) __half g_xt[(size_t)BATCH*HW*CIN]; // [b][p][ci_perm]
__device__ __align__(256) __half g_wh[36*COUT*32];           // [it][co][32ci_perm]

// permutation within a 32-ci chunk: both 16-groups' mma fragment pairs land in
// one 16B span per thread t: halfpos = t*8 + g16*4 + inner
__device__ __host__ __forceinline__ constexpr int permpos32(int c) {
    int k = c & 15, gg = c >> 4;
    return ((k & 7) >> 1) * 8 + gg * 4 + (((k >> 3) << 1) | (k & 1));
}

// ---------------------------------------------------------------------------
__device__ __forceinline__ uint32_t smem_u32(const void* p) {
    uint32_t a;
    asm("{ .reg .u64 t; cvta.to.shared.u64 t, %1; cvt.u32.u64 %0, t; }" : "=r"(a) : "l"(p));
    return a;
}
#define CP_COMMIT() asm volatile("cp.async.commit_group;" ::: "memory")
#define CP_WAIT(n)  asm volatile("cp.async.wait_group %0;" :: "n"(n) : "memory")

__device__ __forceinline__ void lds128(uint32_t& x, uint32_t& y, uint32_t& z,
                                       uint32_t& w, uint32_t a) {
    asm volatile("ld.shared.v4.b32 {%0,%1,%2,%3}, [%4];"
                 : "=r"(x), "=r"(y), "=r"(z), "=r"(w) : "r"(a));
}
__device__ __forceinline__ void mma16(float* c, uint32_t a0, uint32_t a1,
                                      uint32_t a2, uint32_t a3,
                                      uint32_t b0, uint32_t b1) {
    asm volatile(
        "mma.sync.aligned.m16n8k16.row.col.f32.f16.f16.f32 "
        "{%0,%1,%2,%3}, {%4,%5,%6,%7}, {%8,%9}, {%0,%1,%2,%3};"
        : "+f"(c[0]), "+f"(c[1]), "+f"(c[2]), "+f"(c[3])
        : "r"(a0), "r"(a1), "r"(a2), "r"(a3), "r"(b0), "r"(b1));
}

// ---------------------------------------------------------------------------
// prep_x: channel sum-of-squares (fp32) + transpose to [b][p][ci_perm] half
// ---------------------------------------------------------------------------
__global__ void prep_x(const float* __restrict__ x) {
    int idx = blockIdx.x * 256 + threadIdx.x;
    if (idx >= BATCH*HW) return;
    int b = idx / HW, p = idx - b*HW;
    const float* xp = x + (size_t)b*CIN*HW + p;
    float s = 0.f;
    __half hh[128];
#pragma unroll
    for (int c2 = 0; c2 < 4; ++c2)
#pragma unroll
        for (int k = 0; k < 32; ++k) {
            float v = xp[(c2*32 + k) * HW];
            s += v * v;
            hh[c2*32 + permpos32(k)] = __float2half_rn(v);
        }
    g_csum[idx] = s;
    uint4* dst = (uint4*)(g_xt + (size_t)idx * 128);
    const uint4* srcv = (const uint4*)hh;
#pragma unroll
    for (int i = 0; i < 16; ++i) dst[i] = srcv[i];
}

__global__ void inv_kernel() {
    int idx = blockIdx.x * 256 + threadIdx.x;
    if (idx >= BATCH*HW) return;
    int b = idx / HW, p = idx - b*HW;
    int oy = p / WD, ox = p - oy*WD;
    float s = 0.f;
#pragma unroll
    for (int dy = -1; dy <= 1; ++dy) {
        int y = oy + dy; if ((unsigned)y >= HT) continue;
#pragma unroll
        for (int dx = -1; dx <= 1; ++dx) {
            int xq = ox + dx; if ((unsigned)xq >= WD) continue;
            s += g_csum[b*HW + y*WD + xq];
        }
    }
    g_inv[idx] = 1.f / fmaxf(sqrtf(s), 1e-12f);
}

// g_wh[it][co][perm32] where it = cig*9 + pos
__global__ void wtrans_kernel(const float* __restrict__ w) {
    int idx = blockIdx.x * 256 + threadIdx.x;
    if (idx >= 9*CIN*COUT) return;
    int ci  = idx & 127;
    int r   = idx >> 7;
    int co  = r & 255;
    int pos = r >> 8;
    int it  = (ci >> 5) * 9 + pos;
    g_wh[((size_t)it*COUT + co)*32 + permpos32(ci & 31)] =
        __float2half_rn(w[((size_t)co*CIN + ci)*9 + pos]);
}

// ---------------------------------------------------------------------------
// Main conv GEMM: grid (56 px-tiles, 2 cout-tiles, 8 batch), 512 threads.
// fp16 m16n8k16; flat shifted-window B; LDS.128 fragments; 1 sync/tap;
// triple-buffered A, double-buffered window, all via cp.async.
// ---------------------------------------------------------------------------
__global__ __launch_bounds__(512, 1)
void conv_mma_kernel(const float* __restrict__ bias, float* __restrict__ out) {
    extern __shared__ __align__(16) char dyn[];
    const uint32_t sbase = smem_u32(dyn);
    float* sInvF = (float*)(dyn + SINV_OFF);

    const int tid  = threadIdx.x;
    const int wid  = tid >> 5;
    const int lane = tid & 31;
    const int t    = lane & 3;
    const int g    = lane >> 2;
    const int m0w  = (wid & 3) * 32;
    const int n0w  = (wid >> 2) * 56;

    const int p0  = blockIdx.x * NT;
    const int co0 = blockIdx.y * MT;
    const int b   = blockIdx.z;
    const __half* xtb = g_xt + (size_t)b * HW * 128;

    if (tid < NT) sInvF[tid] = g_inv[b * HW + p0 + tid];

    float acc[2][7][4];
#pragma unroll
    for (int mi = 0; mi < 2; ++mi)
#pragma unroll
        for (int ni = 0; ni < 7; ++ni)
#pragma unroll
            for (int q = 0; q < 4; ++q) acc[mi][ni][q] = 0.f;

    auto issueW = [&](int cig) {
        uint32_t wB = sbase + (uint32_t)(cig & 1) * WBUF;
        for (int i = tid; i < WROWS * 4; i += 512) {
            int j = i >> 2, seg = i & 3;
            int q = p0 - 113 + j;
            unsigned ok = ((unsigned)q < (unsigned)HW) ? 16u : 0u;
            int qc = q < 0 ? 0 : (q >= HW ? HW - 1 : q);
            const __half* src = xtb + (size_t)qc * 128 + cig * 32 + seg * 8;
            asm volatile("cp.async.cg.shared.global [%0], [%1], 16, %2;"
                         :: "r"(wB + (uint32_t)(j * RPB + seg * 16)), "l"(src), "r"(ok));
        }
    };
    auto issueA = [&](int it2) {
        // A tile for iteration it2 is a linear 8KB block of g_wh
        uint32_t aB = sbase + AOFF + (uint32_t)(it2 % 3) * A_SZ;
        const __half* src = g_wh + ((size_t)it2 * COUT + co0) * 32 + (size_t)tid * 8;
        asm volatile("cp.async.cg.shared.global [%0], [%1], 16;"
                     :: "r"(aB + (uint32_t)tid * 16), "l"(src));
    };

    issueW(0); issueA(0); CP_COMMIT();

    for (int it = 0; it < 36; ++it) {
        const int tap = it % 9, cig = it / 9;
        if (it < 35) issueA(it + 1);
        if (tap == 4 && cig < 3) issueW(cig + 1);
        CP_COMMIT();
        CP_WAIT(1);
        __syncthreads();

        const int dlt = (tap / 3) * WD + (tap % 3);   // (kh-1)*112+(kw-1)+113
        const uint32_t aB = sbase + AOFF + (uint32_t)(it % 3) * A_SZ;
        const uint32_t wB = sbase + (uint32_t)(cig & 1) * WBUF;
        const uint32_t abase = aB + (uint32_t)((m0w + g) * RPB + t * 16);
        const uint32_t bbase = wB + (uint32_t)((n0w + g + dlt) * RPB + t * 16);

        uint32_t a0[2][2], a1[2][2], a2[2][2], a3[2][2];  // [mi][ks]
#pragma unroll
        for (int mi = 0; mi < 2; ++mi) {
            lds128(a0[mi][0], a2[mi][0], a0[mi][1], a2[mi][1], abase + mi * 1024);
            lds128(a1[mi][0], a3[mi][0], a1[mi][1], a3[mi][1], abase + mi * 1024 + 512);
        }
#pragma unroll
        for (int ni = 0; ni < 7; ++ni) {
            uint32_t b0k0, b1k0, b0k1, b1k1;
            lds128(b0k0, b1k0, b0k1, b1k1, bbase + (uint32_t)ni * 512);
            mma16(acc[0][ni], a0[0][0], a1[0][0], a2[0][0], a3[0][0], b0k0, b1k0);
            mma16(acc[1][ni], a0[1][0], a1[1][0], a2[1][0], a3[1][0], b0k0, b1k0);
            mma16(acc[0][ni], a0[0][1], a1[0][1], a2[0][1], a3[0][1], b0k1, b1k1);
            mma16(acc[1][ni], a0[1][1], a1[1][1], a2[1][1], a3[1][1], b0k1, b1k1);
        }
    }
    __syncthreads();

    // --- epilogue: accum -> smem -> scaled, biased, coalesced STG ---
    float* c_s = (float*)dyn;
#pragma unroll
    for (int mi = 0; mi < 2; ++mi)
#pragma unroll
        for (int ni = 0; ni < 7; ++ni) {
            const int m = m0w + mi * 16 + g;
            const int n = n0w + ni * 8 + 2 * t;
            c_s[m * PC + n]           = acc[mi][ni][0];
            c_s[m * PC + n + 1]       = acc[mi][ni][1];
            c_s[(m + 8) * PC + n]     = acc[mi][ni][2];
            c_s[(m + 8) * PC + n + 1] = acc[mi][ni][3];
        }
    __syncthreads();

    {
        const int m  = tid >> 2;
        const int cb = (tid & 3) * 56;
        const float bv = bias[co0 + m];
        float* op = out + ((size_t)b * COUT + co0 + m) * HW + p0 + cb;
#pragma unroll
        for (int j4 = 0; j4 < 14; ++j4) {
            float4 v = *(const float4*)&c_s[m * PC + cb + j4 * 4];
            float4 r;
            r.x = v.x * sInvF[cb + j4 * 4 + 0] + bv;
            r.y = v.y * sInvF[cb + j4 * 4 + 1] + bv;
            r.z = v.z * sInvF[cb + j4 * 4 + 2] + bv;
            r.w = v.w * sInvF[cb + j4 * 4 + 3] + bv;
            *(float4*)&op[j4 * 4] = r;
        }
    }
}

// ---------------------------------------------------------------------------
// Edge fixup: subtract row-wrap garbage at ox==0 (kw=0) / ox==111 (kw=2).
// Same half-rounded values as the main kernel (fp32 products exact).
// ---------------------------------------------------------------------------
__global__ void fixup_kernel(float* __restrict__ out) {
    const int side = blockIdx.z;
    const int b    = blockIdx.y;
    const int oc   = blockIdx.x * 16;
    const int co   = threadIdx.x;

    __shared__ __half xc[18][128];
    for (int i = threadIdx.x; i < 18 * 16; i += 256) {
        int r = i >> 4, seg = i & 15;
        int q = 0; bool v;
        if (side == 0) { int row = oc - 1 + r; v = (row >= 1 && row <= HT); q = row * WD - 1; }
        else           { int row = oc + r;     v = (row <= HT - 1);         q = row * WD;     }
        uint4 val = make_uint4(0, 0, 0, 0);
        if (v) val = *(const uint4*)(g_xt + ((size_t)b * HW + q) * 128 + seg * 8);
        *(uint4*)&xc[r][seg * 8] = val;
    }
    __syncthreads();

    const int kwsel = side ? 2 : 0;
    float corr[16];
#pragma unroll
    for (int dy = 0; dy < 16; ++dy) corr[dy] = 0.f;

#pragma unroll
    for (int kh = 0; kh < 3; ++kh) {
        const int pos = kh * 3 + kwsel;
        for (int cig = 0; cig < 4; ++cig) {
            const __half* wrow = g_wh + ((size_t)(cig * 9 + pos) * COUT + co) * 32;
#pragma unroll
            for (int c32 = 0; c32 < 32; ++c32) {
                float w = __half2float(wrow[c32]);
#pragma unroll
                for (int dy = 0; dy < 16; ++dy)
                    corr[dy] += w * __half2float(xc[dy + kh][cig * 32 + c32]);
            }
        }
    }

    const int edge = side ? (WD - 1) : 0;
#pragma unroll
    for (int dy = 0; dy < 16; ++dy) {
        int oy = oc + dy;
        float inv = g_inv[b * HW + oy * WD + edge];
        size_t o = ((size_t)b * COUT + co) * HW + (size_t)oy * WD + edge;
        out[o] -= corr[dy] * inv;
    }
}

// ---------------------------------------------------------------------------
extern "C" void kernel_launch(void* const* d_in, const int* in_sizes, int n_in,
                              void* d_out, int out_size) {
    const float* x    = (const float*)d_in[0];
    const float* wgt  = (const float*)d_in[1];
    const float* bias = (const float*)d_in[2];
    float* out        = (float*)d_out;

    cudaFuncSetAttribute(conv_mma_kernel,
                         cudaFuncAttributeMaxDynamicSharedMemorySize, DSMEM);

    int npix = BATCH * HW;
    prep_x<<<(npix + 255) / 256, 256>>>(x);
    inv_kernel<<<(npix + 255) / 256, 256>>>();
    wtrans_kernel<<<(9 * CIN * COUT + 255) / 256, 256>>>(wgt);

    conv_mma_kernel<<<dim3(56, 2, 8), 512, DSMEM>>>(bias, out);
    fixup_kernel<<<dim3(7, 8, 2), 256>>>(out);
}

// round 9
// speedup vs baseline: 6.7272x; 1.1344x over previous
#include <cuda_runtime.h>
#include <cuda_fp16.h>
#include <cstdint>
#include <cstddef>

#define BATCH 8
#define CIN   128
#define HT    112
#define WD    112
#define COUT  256
#define HW    (HT*WD)

#define NT    224          // pixels per CTA (2 rows)
#define MT    128          // couts per CTA
#define WROWS 450          // staged window rows
#define RPB   64           // bytes per row (32 halves, conflict-free LDS.128)
#define WBUF  (WROWS*RPB)  // 28800
#define A_SZ  (MT*RPB)     // 8192
#define AOFF  (2*WBUF)     // 57600; 4 A buffers follow (32768) -> 90368
#define PC    228          // epilogue fp32 pitch
#define SINV_OFF 116736    // after c_s (128*228*4)
#define DSMEM 117632

__device__ float g_csum[BATCH*HW];
__device__ float g_inv [BATCH*HW];
__device__ __align__(256) __half g_xt[(size_t)BATCH*HW*CIN]; // [b][p][ci_perm]
__device__ __align__(256) __half g_wh[36*COUT*32];           // [it][co][32ci_perm]

// permutation within a 32-ci chunk: both 16-groups' mma fragment pairs land in
// one 16B span per thread t: halfpos = t*8 + g16*4 + inner
__device__ __host__ __forceinline__ constexpr int permpos32(int c) {
    int k = c & 15, gg = c >> 4;
    return ((k & 7) >> 1) * 8 + gg * 4 + (((k >> 3) << 1) | (k & 1));
}

// ---------------------------------------------------------------------------
__device__ __forceinline__ uint32_t smem_u32(const void* p) {
    uint32_t a;
    asm("{ .reg .u64 t; cvta.to.shared.u64 t, %1; cvt.u32.u64 %0, t; }" : "=r"(a) : "l"(p));
    return a;
}
#define CP_COMMIT() asm volatile("cp.async.commit_group;" ::: "memory")
#define CP_WAIT(n)  asm volatile("cp.async.wait_group %0;" :: "n"(n) : "memory")

__device__ __forceinline__ void lds128(uint32_t& x, uint32_t& y, uint32_t& z,
                                       uint32_t& w, uint32_t a) {
    asm volatile("ld.shared.v4.b32 {%0,%1,%2,%3}, [%4];"
                 : "=r"(x), "=r"(y), "=r"(z), "=r"(w) : "r"(a));
}
__device__ __forceinline__ void mma16(float* c, uint32_t a0, uint32_t a1,
                                      uint32_t a2, uint32_t a3,
                                      uint32_t b0, uint32_t b1) {
    asm volatile(
        "mma.sync.aligned.m16n8k16.row.col.f32.f16.f16.f32 "
        "{%0,%1,%2,%3}, {%4,%5,%6,%7}, {%8,%9}, {%0,%1,%2,%3};"
        : "+f"(c[0]), "+f"(c[1]), "+f"(c[2]), "+f"(c[3])
        : "r"(a0), "r"(a1), "r"(a2), "r"(a3), "r"(b0), "r"(b1));
}

// ---------------------------------------------------------------------------
// prep_x: channel sum-of-squares (fp32) + transpose to [b][p][ci_perm] half
// ---------------------------------------------------------------------------
__global__ void prep_x(const float* __restrict__ x) {
    int idx = blockIdx.x * 256 + threadIdx.x;
    if (idx >= BATCH*HW) return;
    int b = idx / HW, p = idx - b*HW;
    const float* xp = x + (size_t)b*CIN*HW + p;
    float s = 0.f;
    __half hh[128];
#pragma unroll
    for (int c2 = 0; c2 < 4; ++c2)
#pragma unroll
        for (int k = 0; k < 32; ++k) {
            float v = xp[(c2*32 + k) * HW];
            s += v * v;
            hh[c2*32 + permpos32(k)] = __float2half_rn(v);
        }
    g_csum[idx] = s;
    uint4* dst = (uint4*)(g_xt + (size_t)idx * 128);
    const uint4* srcv = (const uint4*)hh;
#pragma unroll
    for (int i = 0; i < 16; ++i) dst[i] = srcv[i];
}

__global__ void inv_kernel() {
    int idx = blockIdx.x * 256 + threadIdx.x;
    if (idx >= BATCH*HW) return;
    int b = idx / HW, p = idx - b*HW;
    int oy = p / WD, ox = p - oy*WD;
    float s = 0.f;
#pragma unroll
    for (int dy = -1; dy <= 1; ++dy) {
        int y = oy + dy; if ((unsigned)y >= HT) continue;
#pragma unroll
        for (int dx = -1; dx <= 1; ++dx) {
            int xq = ox + dx; if ((unsigned)xq >= WD) continue;
            s += g_csum[b*HW + y*WD + xq];
        }
    }
    g_inv[idx] = 1.f / fmaxf(sqrtf(s), 1e-12f);
}

// g_wh[it][co][perm32] where it = cig*9 + pos
__global__ void wtrans_kernel(const float* __restrict__ w) {
    int idx = blockIdx.x * 256 + threadIdx.x;
    if (idx >= 9*CIN*COUT) return;
    int ci  = idx & 127;
    int r   = idx >> 7;
    int co  = r & 255;
    int pos = r >> 8;
    int it  = (ci >> 5) * 9 + pos;
    g_wh[((size_t)it*COUT + co)*32 + permpos32(ci & 31)] =
        __float2half_rn(w[((size_t)co*CIN + ci)*9 + pos]);
}

// ---------------------------------------------------------------------------
// Main conv GEMM: grid (56 px-tiles, 2 cout-tiles, 8 batch), 512 threads.
// Fully unrolled 36-tap loop (all smem addressing compile-time); barrier
// every 2 taps; 4-deep cp.async A pipeline; double-buffered window.
// ---------------------------------------------------------------------------
__global__ __launch_bounds__(512, 1)
void conv_mma_kernel(const float* __restrict__ bias, float* __restrict__ out) {
    extern __shared__ __align__(16) char dyn[];
    const uint32_t sbase = smem_u32(dyn);
    float* sInvF = (float*)(dyn + SINV_OFF);

    const int tid  = threadIdx.x;
    const int wid  = tid >> 5;
    const int lane = tid & 31;
    const int t    = lane & 3;
    const int g    = lane >> 2;
    const int m0w  = (wid & 3) * 32;
    const int n0w  = (wid >> 2) * 56;

    const int p0  = blockIdx.x * NT;
    const int co0 = blockIdx.y * MT;
    const int b   = blockIdx.z;
    const __half* xtb = g_xt + (size_t)b * HW * 128;

    if (tid < NT) sInvF[tid] = g_inv[b * HW + p0 + tid];

    float acc[2][7][4];
#pragma unroll
    for (int mi = 0; mi < 2; ++mi)
#pragma unroll
        for (int ni = 0; ni < 7; ++ni)
#pragma unroll
            for (int q = 0; q < 4; ++q) acc[mi][ni][q] = 0.f;

    // thread-constant pieces of the fragment addresses
    const uint32_t aTh = sbase + AOFF + (uint32_t)((m0w + g) * RPB + t * 16);
    const uint32_t bTh = sbase + (uint32_t)((n0w + g) * RPB + t * 16);

    auto issueW = [&](int cig) {
        uint32_t wB = sbase + (uint32_t)(cig & 1) * WBUF;
        for (int i = tid; i < WROWS * 4; i += 512) {
            int j = i >> 2, seg = i & 3;
            int q = p0 - 113 + j;
            unsigned ok = ((unsigned)q < (unsigned)HW) ? 16u : 0u;
            int qc = q < 0 ? 0 : (q >= HW ? HW - 1 : q);
            const __half* src = xtb + (size_t)qc * 128 + cig * 32 + seg * 8;
            asm volatile("cp.async.cg.shared.global [%0], [%1], 16, %2;"
                         :: "r"(wB + (uint32_t)(j * RPB + seg * 16)), "l"(src), "r"(ok));
        }
    };
    auto issueA = [&](int it2) {
        uint32_t aB = sbase + AOFF + (uint32_t)(it2 & 3) * A_SZ;
        const __half* src = g_wh + ((size_t)it2 * COUT + co0) * 32 + (size_t)tid * 8;
        asm volatile("cp.async.cg.shared.global [%0], [%1], 16;"
                     :: "r"(aB + (uint32_t)tid * 16), "l"(src));
    };

    issueW(0); issueA(0); CP_COMMIT();   // G0 = {W0, A0}
    issueA(1); CP_COMMIT();              // G1 = {A1}

#pragma unroll
    for (int it = 0; it < 36; ++it) {
        const int tap = it % 9, cig = it / 9;   // compile-time after unroll

        if (it + 2 < 36) issueA(it + 2);
        if (tap == 4 && cig < 3) issueW(cig + 1);
        CP_COMMIT();                             // G(it+2)
        if ((it & 1) == 0) {
            CP_WAIT(1);                          // G0..G(it+1) complete
            __syncthreads();                     // ...and visible to all
        }

        const int dlt = (tap / 3) * WD + (tap % 3);
        const uint32_t abase = aTh + (uint32_t)(it & 3) * A_SZ;
        const uint32_t bbase = bTh + (uint32_t)((cig & 1) * WBUF + dlt * RPB);

        uint32_t a0[2][2], a1[2][2], a2[2][2], a3[2][2];  // [mi][ks]
#pragma unroll
        for (int mi = 0; mi < 2; ++mi) {
            lds128(a0[mi][0], a2[mi][0], a0[mi][1], a2[mi][1], abase + mi * 1024);
            lds128(a1[mi][0], a3[mi][0], a1[mi][1], a3[mi][1], abase + mi * 1024 + 512);
        }
#pragma unroll
        for (int ni = 0; ni < 7; ++ni) {
            uint32_t b0k0, b1k0, b0k1, b1k1;
            lds128(b0k0, b1k0, b0k1, b1k1, bbase + (uint32_t)ni * 512);
            mma16(acc[0][ni], a0[0][0], a1[0][0], a2[0][0], a3[0][0], b0k0, b1k0);
            mma16(acc[1][ni], a0[1][0], a1[1][0], a2[1][0], a3[1][0], b0k0, b1k0);
            mma16(acc[0][ni], a0[0][1], a1[0][1], a2[0][1], a3[0][1], b0k1, b1k1);
            mma16(acc[1][ni], a0[1][1], a1[1][1], a2[1][1], a3[1][1], b0k1, b1k1);
        }
    }
    __syncthreads();

    // --- epilogue: accum -> smem -> scaled, biased, coalesced STG ---
    float* c_s = (float*)dyn;
#pragma unroll
    for (int mi = 0; mi < 2; ++mi)
#pragma unroll
        for (int ni = 0; ni < 7; ++ni) {
            const int m = m0w + mi * 16 + g;
            const int n = n0w + ni * 8 + 2 * t;
            c_s[m * PC + n]           = acc[mi][ni][0];
            c_s[m * PC + n + 1]       = acc[mi][ni][1];
            c_s[(m + 8) * PC + n]     = acc[mi][ni][2];
            c_s[(m + 8) * PC + n + 1] = acc[mi][ni][3];
        }
    __syncthreads();

    {
        const int m  = tid >> 2;
        const int cb = (tid & 3) * 56;
        const float bv = bias[co0 + m];
        float* op = out + ((size_t)b * COUT + co0 + m) * HW + p0 + cb;
#pragma unroll
        for (int j4 = 0; j4 < 14; ++j4) {
            float4 v = *(const float4*)&c_s[m * PC + cb + j4 * 4];
            float4 r;
            r.x = v.x * sInvF[cb + j4 * 4 + 0] + bv;
            r.y = v.y * sInvF[cb + j4 * 4 + 1] + bv;
            r.z = v.z * sInvF[cb + j4 * 4 + 2] + bv;
            r.w = v.w * sInvF[cb + j4 * 4 + 3] + bv;
            *(float4*)&op[j4 * 4] = r;
        }
    }
}

// ---------------------------------------------------------------------------
// Edge fixup: subtract row-wrap garbage at ox==0 (kw=0) / ox==111 (kw=2).
// Same half-rounded values as the main kernel (fp32 products exact).
// ---------------------------------------------------------------------------
__global__ void fixup_kernel(float* __restrict__ out) {
    const int side = blockIdx.z;
    const int b    = blockIdx.y;
    const int oc   = blockIdx.x * 16;
    const int co   = threadIdx.x;

    __shared__ __half xc[18][128];
    for (int i = threadIdx.x; i < 18 * 16; i += 256) {
        int r = i >> 4, seg = i & 15;
        int q = 0; bool v;
        if (side == 0) { int row = oc - 1 + r; v = (row >= 1 && row <= HT); q = row * WD - 1; }
        else           { int row = oc + r;     v = (row <= HT - 1);         q = row * WD;     }
        uint4 val = make_uint4(0, 0, 0, 0);
        if (v) val = *(const uint4*)(g_xt + ((size_t)b * HW + q) * 128 + seg * 8);
        *(uint4*)&xc[r][seg * 8] = val;
    }
    __syncthreads();

    const int kwsel = side ? 2 : 0;
    float corr[16];
#pragma unroll
    for (int dy = 0; dy < 16; ++dy) corr[dy] = 0.f;

#pragma unroll
    for (int kh = 0; kh < 3; ++kh) {
        const int pos = kh * 3 + kwsel;
        for (int cig = 0; cig < 4; ++cig) {
            const __half* wrow = g_wh + ((size_t)(cig * 9 + pos) * COUT + co) * 32;
#pragma unroll
            for (int c32 = 0; c32 < 32; ++c32) {
                float w = __half2float(wrow[c32]);
#pragma unroll
                for (int dy = 0; dy < 16; ++dy)
                    corr[dy] += w * __half2float(xc[dy + kh][cig * 32 + c32]);
            }
        }
    }

    const int edge = side ? (WD - 1) : 0;
#pragma unroll
    for (int dy = 0; dy < 16; ++dy) {
        int oy = oc + dy;
        float inv = g_inv[b * HW + oy * WD + edge];
        size_t o = ((size_t)b * COUT + co) * HW + (size_t)oy * WD + edge;
        out[o] -= corr[dy] * inv;
    }
}

// ---------------------------------------------------------------------------
extern "C" void kernel_launch(void* const* d_in, const int* in_sizes, int n_in,
                              void* d_out, int out_size) {
    const float* x    = (const float*)d_in[0];
    const float* wgt  = (const float*)d_in[1];
    const float* bias = (const float*)d_in[2];
    float* out        = (float*)d_out;

    cudaFuncSetAttribute(conv_mma_kernel,
                         cudaFuncAttributeMaxDynamicSharedMemorySize, DSMEM);

    int npix = BATCH * HW;
    prep_x<<<(npix + 255) / 256, 256>>>(x);
    inv_kernel<<<(npix + 255) / 256, 256>>>();
    wtrans_kernel<<<(9 * CIN * COUT + 255) / 256, 256>>>(wgt);

    conv_mma_kernel<<<dim3(56, 2, 8), 512, DSMEM>>>(bias, out);
    fixup_kernel<<<dim3(7, 8, 2), 256>>>(out);
}

// round 10
// speedup vs baseline: 7.0922x; 1.0543x over previous
#include <cuda_runtime.h>
#include <cuda_fp16.h>
#include <cstdint>
#include <cstddef>

#define BATCH 8
#define CIN   128
#define HT    112
#define WD    112
#define COUT  256
#define HW    (HT*WD)

#define NT    112          // pixels per CTA (1 image row)
#define MT    128          // couts per CTA
#define WROWS 338          // staged window rows (NT + 226)
#define RPB   64           // bytes per row (32 halves, conflict-free LDS.128)
#define WBUF  (WROWS*RPB)  // 21632
#define A_SZ  (MT*RPB)     // 8192
#define AOFF  (2*WBUF)     // 43264; 4 A buffers follow -> 76032
#define PC    116          // epilogue fp32 pitch
#define SINV_OFF 76032
#define DSMEM 76544

__device__ float g_csum[BATCH*HW];
__device__ float g_inv [BATCH*HW];
__device__ __align__(256) __half g_xt[(size_t)BATCH*HW*CIN]; // [b][p][ci_perm]
__device__ __align__(256) __half g_wh[36*COUT*32];           // [it][co][32ci_perm]

// permutation within a 32-ci chunk: both 16-groups' mma fragment pairs land in
// one 16B span per thread t: halfpos = t*8 + g16*4 + inner
__device__ __host__ __forceinline__ constexpr int permpos32(int c) {
    int k = c & 15, gg = c >> 4;
    return ((k & 7) >> 1) * 8 + gg * 4 + (((k >> 3) << 1) | (k & 1));
}

// ---------------------------------------------------------------------------
__device__ __forceinline__ uint32_t smem_u32(const void* p) {
    uint32_t a;
    asm("{ .reg .u64 t; cvta.to.shared.u64 t, %1; cvt.u32.u64 %0, t; }" : "=r"(a) : "l"(p));
    return a;
}
#define CP_COMMIT() asm volatile("cp.async.commit_group;" ::: "memory")
#define CP_WAIT(n)  asm volatile("cp.async.wait_group %0;" :: "n"(n) : "memory")

__device__ __forceinline__ void lds128(uint32_t& x, uint32_t& y, uint32_t& z,
                                       uint32_t& w, uint32_t a) {
    asm volatile("ld.shared.v4.b32 {%0,%1,%2,%3}, [%4];"
                 : "=r"(x), "=r"(y), "=r"(z), "=r"(w) : "r"(a));
}
__device__ __forceinline__ void mma16(float* c, uint32_t a0, uint32_t a1,
                                      uint32_t a2, uint32_t a3,
                                      uint32_t b0, uint32_t b1) {
    asm volatile(
        "mma.sync.aligned.m16n8k16.row.col.f32.f16.f16.f32 "
        "{%0,%1,%2,%3}, {%4,%5,%6,%7}, {%8,%9}, {%0,%1,%2,%3};"
        : "+f"(c[0]), "+f"(c[1]), "+f"(c[2]), "+f"(c[3])
        : "r"(a0), "r"(a1), "r"(a2), "r"(a3), "r"(b0), "r"(b1));
}

// ---------------------------------------------------------------------------
// prep_x: channel sum-of-squares (fp32) + transpose to [b][p][ci_perm] half.
// 128 threads / 128 pixels per block; smem-staged fully-coalesced output.
// ---------------------------------------------------------------------------
__global__ __launch_bounds__(128)
void prep_x(const float* __restrict__ x) {
    __shared__ __half sh[128][136];     // pad 8 halves: conflict-free STS/LDS.128
    const int tid = threadIdx.x;
    const int idx = blockIdx.x * 128 + tid;     // HW % 128 == 0 -> same b per blk
    const int b = idx / HW, p = idx - b * HW;
    const float* xp = x + (size_t)b * CIN * HW + p;

    float s = 0.f;
    __half hh[128];
#pragma unroll
    for (int c2 = 0; c2 < 4; ++c2)
#pragma unroll
        for (int k = 0; k < 32; ++k) {
            float v = xp[(c2 * 32 + k) * HW];
            s += v * v;
            hh[c2 * 32 + permpos32(k)] = __float2half_rn(v);
        }
    g_csum[idx] = s;
#pragma unroll
    for (int i = 0; i < 16; ++i)
        *(uint4*)&sh[tid][i * 8] = ((const uint4*)hh)[i];
    __syncthreads();

    uint4* dst = (uint4*)(g_xt + ((size_t)blockIdx.x * 128) * 128);
    for (int i = tid; i < 2048; i += 128) {
        int px = i >> 4, seg = i & 15;
        dst[i] = *(const uint4*)&sh[px][seg * 8];
    }
}

__global__ void inv_kernel() {
    int idx = blockIdx.x * 256 + threadIdx.x;
    if (idx >= BATCH*HW) return;
    int b = idx / HW, p = idx - b*HW;
    int oy = p / WD, ox = p - oy*WD;
    float s = 0.f;
#pragma unroll
    for (int dy = -1; dy <= 1; ++dy) {
        int y = oy + dy; if ((unsigned)y >= HT) continue;
#pragma unroll
        for (int dx = -1; dx <= 1; ++dx) {
            int xq = ox + dx; if ((unsigned)xq >= WD) continue;
            s += g_csum[b*HW + y*WD + xq];
        }
    }
    g_inv[idx] = 1.f / fmaxf(sqrtf(s), 1e-12f);
}

// g_wh[it][co][perm32] where it = cig*9 + pos
__global__ void wtrans_kernel(const float* __restrict__ w) {
    int idx = blockIdx.x * 256 + threadIdx.x;
    if (idx >= 9*CIN*COUT) return;
    int ci  = idx & 127;
    int r   = idx >> 7;
    int co  = r & 255;
    int pos = r >> 8;
    int it  = (ci >> 5) * 9 + pos;
    g_wh[((size_t)it*COUT + co)*32 + permpos32(ci & 31)] =
        __float2half_rn(w[((size_t)co*CIN + ci)*9 + pos]);
}

// ---------------------------------------------------------------------------
// Main conv GEMM: grid (112 px-tiles, 2 cout-tiles, 8 batch), 256 threads,
// 2 CTAs/SM. Fully unrolled 36-tap loop; barrier every 2 taps; 4-deep A
// pipeline; double-buffered window.
// ---------------------------------------------------------------------------
__global__ __launch_bounds__(256, 2)
void conv_mma_kernel(const float* __restrict__ bias, float* __restrict__ out) {
    extern __shared__ __align__(16) char dyn[];
    const uint32_t sbase = smem_u32(dyn);
    float* sInvF = (float*)(dyn + SINV_OFF);

    const int tid  = threadIdx.x;
    const int wid  = tid >> 5;
    const int lane = tid & 31;
    const int t    = lane & 3;
    const int g    = lane >> 2;
    const int m0w  = (wid & 3) * 32;
    const int n0w  = (wid >> 2) * 56;

    const int p0  = blockIdx.x * NT;
    const int co0 = blockIdx.y * MT;
    const int b   = blockIdx.z;
    const __half* xtb = g_xt + (size_t)b * HW * 128;

    if (tid < NT) sInvF[tid] = g_inv[b * HW + p0 + tid];

    float acc[2][7][4];
#pragma unroll
    for (int mi = 0; mi < 2; ++mi)
#pragma unroll
        for (int ni = 0; ni < 7; ++ni)
#pragma unroll
            for (int q = 0; q < 4; ++q) acc[mi][ni][q] = 0.f;

    // thread-constant pieces of the fragment addresses
    const uint32_t aTh = sbase + AOFF + (uint32_t)((m0w + g) * RPB + t * 16);
    const uint32_t bTh = sbase + (uint32_t)((n0w + g) * RPB + t * 16);

    auto issueW = [&](int cig) {
        uint32_t wB = sbase + (uint32_t)(cig & 1) * WBUF;
        for (int i = tid; i < WROWS * 4; i += 256) {
            int j = i >> 2, seg = i & 3;
            int q = p0 - 113 + j;
            unsigned ok = ((unsigned)q < (unsigned)HW) ? 16u : 0u;
            int qc = q < 0 ? 0 : (q >= HW ? HW - 1 : q);
            const __half* src = xtb + (size_t)qc * 128 + cig * 32 + seg * 8;
            asm volatile("cp.async.cg.shared.global [%0], [%1], 16, %2;"
                         :: "r"(wB + (uint32_t)(j * RPB + seg * 16)), "l"(src), "r"(ok));
        }
    };
    auto issueA = [&](int it2) {
        uint32_t aB = sbase + AOFF + (uint32_t)(it2 & 3) * A_SZ;
        const __half* src = g_wh + ((size_t)it2 * COUT + co0) * 32 + (size_t)tid * 16;
        asm volatile("cp.async.cg.shared.global [%0], [%1], 16;"
                     :: "r"(aB + (uint32_t)tid * 32), "l"(src));
        asm volatile("cp.async.cg.shared.global [%0], [%1], 16;"
                     :: "r"(aB + (uint32_t)tid * 32 + 16), "l"(src + 8));
    };

    issueW(0); issueA(0); CP_COMMIT();   // G0 = {W0, A0}
    issueA(1); CP_COMMIT();              // G1 = {A1}

#pragma unroll
    for (int it = 0; it < 36; ++it) {
        const int tap = it % 9, cig = it / 9;   // compile-time after unroll

        if (it + 2 < 36) issueA(it + 2);
        if (tap == 4 && cig < 3) issueW(cig + 1);
        CP_COMMIT();                             // G(it+2)
        if ((it & 1) == 0) {
            CP_WAIT(1);                          // G0..G(it+1) complete
            __syncthreads();                     // ...and visible to all
        }

        const int dlt = (tap / 3) * WD + (tap % 3);
        const uint32_t abase = aTh + (uint32_t)(it & 3) * A_SZ;
        const uint32_t bbase = bTh + (uint32_t)((cig & 1) * WBUF + dlt * RPB);

        uint32_t a0[2][2], a1[2][2], a2[2][2], a3[2][2];  // [mi][ks]
#pragma unroll
        for (int mi = 0; mi < 2; ++mi) {
            lds128(a0[mi][0], a2[mi][0], a0[mi][1], a2[mi][1], abase + mi * 1024);
            lds128(a1[mi][0], a3[mi][0], a1[mi][1], a3[mi][1], abase + mi * 1024 + 512);
        }
#pragma unroll
        for (int ni = 0; ni < 7; ++ni) {
            uint32_t b0k0, b1k0, b0k1, b1k1;
            lds128(b0k0, b1k0, b0k1, b1k1, bbase + (uint32_t)ni * 512);
            mma16(acc[0][ni], a0[0][0], a1[0][0], a2[0][0], a3[0][0], b0k0, b1k0);
            mma16(acc[1][ni], a0[1][0], a1[1][0], a2[1][0], a3[1][0], b0k0, b1k0);
            mma16(acc[0][ni], a0[0][1], a1[0][1], a2[0][1], a3[0][1], b0k1, b1k1);
            mma16(acc[1][ni], a0[1][1], a1[1][1], a2[1][1], a3[1][1], b0k1, b1k1);
        }
    }
    __syncthreads();

    // --- epilogue: accum -> smem -> scaled, biased, coalesced STG ---
    float* c_s = (float*)dyn;
#pragma unroll
    for (int mi = 0; mi < 2; ++mi)
#pragma unroll
        for (int ni = 0; ni < 7; ++ni) {
            const int m = m0w + mi * 16 + g;
            const int n = n0w + ni * 8 + 2 * t;
            c_s[m * PC + n]           = acc[mi][ni][0];
            c_s[m * PC + n + 1]       = acc[mi][ni][1];
            c_s[(m + 8) * PC + n]     = acc[mi][ni][2];
            c_s[(m + 8) * PC + n + 1] = acc[mi][ni][3];
        }
    __syncthreads();

    {
        const int m  = tid >> 1;
        const int cb = (tid & 1) * 56;
        const float bv = bias[co0 + m];
        float* op = out + ((size_t)b * COUT + co0 + m) * HW + p0 + cb;
#pragma unroll
        for (int j4 = 0; j4 < 14; ++j4) {
            float4 v = *(const float4*)&c_s[m * PC + cb + j4 * 4];
            float4 r;
            r.x = v.x * sInvF[cb + j4 * 4 + 0] + bv;
            r.y = v.y * sInvF[cb + j4 * 4 + 1] + bv;
            r.z = v.z * sInvF[cb + j4 * 4 + 2] + bv;
            r.w = v.w * sInvF[cb + j4 * 4 + 3] + bv;
            *(float4*)&op[j4 * 4] = r;
        }
    }
}

// ---------------------------------------------------------------------------
// Edge fixup: subtract row-wrap garbage at ox==0 (kw=0) / ox==111 (kw=2).
// Same half-rounded values as the main kernel (fp32 products exact).
// ---------------------------------------------------------------------------
__global__ void fixup_kernel(float* __restrict__ out) {
    const int side = blockIdx.z;
    const int b    = blockIdx.y;
    const int oc   = blockIdx.x * 16;
    const int co   = threadIdx.x;

    __shared__ __half xc[18][128];
    for (int i = threadIdx.x; i < 18 * 16; i += 256) {
        int r = i >> 4, seg = i & 15;
        int q = 0; bool v;
        if (side == 0) { int row = oc - 1 + r; v = (row >= 1 && row <= HT); q = row * WD - 1; }
        else           { int row = oc + r;     v = (row <= HT - 1);         q = row * WD;     }
        uint4 val = make_uint4(0, 0, 0, 0);
        if (v) val = *(const uint4*)(g_xt + ((size_t)b * HW + q) * 128 + seg * 8);
        *(uint4*)&xc[r][seg * 8] = val;
    }
    __syncthreads();

    const int kwsel = side ? 2 : 0;
    float corr[16];
#pragma unroll
    for (int dy = 0; dy < 16; ++dy) corr[dy] = 0.f;

#pragma unroll
    for (int kh = 0; kh < 3; ++kh) {
        const int pos = kh * 3 + kwsel;
        for (int cig = 0; cig < 4; ++cig) {
            const __half* wrow = g_wh + ((size_t)(cig * 9 + pos) * COUT + co) * 32;
#pragma unroll
            for (int c32 = 0; c32 < 32; ++c32) {
                float w = __half2float(wrow[c32]);
#pragma unroll
                for (int dy = 0; dy < 16; ++dy)
                    corr[dy] += w * __half2float(xc[dy + kh][cig * 32 + c32]);
            }
        }
    }

    const int edge = side ? (WD - 1) : 0;
#pragma unroll
    for (int dy = 0; dy < 16; ++dy) {
        int oy = oc + dy;
        float inv = g_inv[b * HW + oy * WD + edge];
        size_t o = ((size_t)b * COUT + co) * HW + (size_t)oy * WD + edge;
        out[o] -= corr[dy] * inv;
    }
}

// ---------------------------------------------------------------------------
extern "C" void kernel_launch(void* const* d_in, const int* in_sizes, int n_in,
                              void* d_out, int out_size) {
    const float* x    = (const float*)d_in[0];
    const float* wgt  = (const float*)d_in[1];
    const float* bias = (const float*)d_in[2];
    float* out        = (float*)d_out;

    cudaFuncSetAttribute(conv_mma_kernel,
                         cudaFuncAttributeMaxDynamicSharedMemorySize, DSMEM);

    int npix = BATCH * HW;
    prep_x<<<npix / 128, 128>>>(x);
    inv_kernel<<<(npix + 255) / 256, 256>>>();
    wtrans_kernel<<<(9 * CIN * COUT + 255) / 256, 256>>>(wgt);

    conv_mma_kernel<<<dim3(112, 2, 8), 256, DSMEM>>>(bias, out);
    fixup_kernel<<<dim3(7, 8, 2), 256>>>(out);
}

// round 11
// speedup vs baseline: 7.7851x; 1.0977x over previous
#include <cuda_runtime.h>
#include <cuda_fp16.h>
#include <cstdint>
#include <cstddef>

#define BATCH 8
#define CIN   128
#define HT    112
#define WD    112
#define COUT  256
#define HW    (HT*WD)

#define NT    112          // pixels per CTA (1 image row)
#define MT    128          // couts per CTA
#define WROWS 338          // staged window rows (NT + 226)
#define RPB   64           // bytes per row (32 halves, conflict-free LDS.128)
#define WBUF  (WROWS*RPB)  // 21632
#define A_SZ  (MT*RPB)     // 8192
#define AOFF  (2*WBUF)     // 43264; 4 A buffers follow -> 76032
#define PC    116          // epilogue fp32 pitch
#define SINV_OFF 76032     // 112 floats
#define SCORR_OFF 76544    // 256 floats (L then R)
#define DSMEM 77568

__device__ float g_csum[BATCH*HW];
__device__ float g_corr[BATCH*HT*2*COUT];                    // [b][oy][side][co]
__device__ __align__(256) __half g_xt[(size_t)BATCH*HW*CIN]; // [b][p][ci_perm]
__device__ __align__(256) __half g_wh[36*COUT*32];           // [it][co][32ci_perm]

// permutation within a 32-ci chunk: both 16-groups' mma fragment pairs land in
// one 16B span per thread t: halfpos = t*8 + g16*4 + inner
__device__ __host__ __forceinline__ constexpr int permpos32(int c) {
    int k = c & 15, gg = c >> 4;
    return ((k & 7) >> 1) * 8 + gg * 4 + (((k >> 3) << 1) | (k & 1));
}

// ---------------------------------------------------------------------------
__device__ __forceinline__ uint32_t smem_u32(const void* p) {
    uint32_t a;
    asm("{ .reg .u64 t; cvta.to.shared.u64 t, %1; cvt.u32.u64 %0, t; }" : "=r"(a) : "l"(p));
    return a;
}
#define CP_COMMIT() asm volatile("cp.async.commit_group;" ::: "memory")
#define CP_WAIT(n)  asm volatile("cp.async.wait_group %0;" :: "n"(n) : "memory")

__device__ __forceinline__ void lds128(uint32_t& x, uint32_t& y, uint32_t& z,
                                       uint32_t& w, uint32_t a) {
    asm volatile("ld.shared.v4.b32 {%0,%1,%2,%3}, [%4];"
                 : "=r"(x), "=r"(y), "=r"(z), "=r"(w) : "r"(a));
}
__device__ __forceinline__ void mma16(float* c, uint32_t a0, uint32_t a1,
                                      uint32_t a2, uint32_t a3,
                                      uint32_t b0, uint32_t b1) {
    asm volatile(
        "mma.sync.aligned.m16n8k16.row.col.f32.f16.f16.f32 "
        "{%0,%1,%2,%3}, {%4,%5,%6,%7}, {%8,%9}, {%0,%1,%2,%3};"
        : "+f"(c[0]), "+f"(c[1]), "+f"(c[2]), "+f"(c[3])
        : "r"(a0), "r"(a1), "r"(a2), "r"(a3), "r"(b0), "r"(b1));
}

// ---------------------------------------------------------------------------
// prep_x: channel sum-of-squares (fp32) + transpose to [b][p][ci_perm] half.
// 128 threads / 128 pixels per block; smem-staged fully-coalesced output.
// ---------------------------------------------------------------------------
__global__ __launch_bounds__(128)
void prep_x(const float* __restrict__ x) {
    __shared__ __half sh[128][136];     // pad 8 halves: conflict-free STS/LDS.128
    const int tid = threadIdx.x;
    const int idx = blockIdx.x * 128 + tid;     // HW % 128 == 0 -> same b per blk
    const int b = idx / HW, p = idx - b * HW;
    const float* xp = x + (size_t)b * CIN * HW + p;

    float s = 0.f;
    __half hh[128];
#pragma unroll
    for (int c2 = 0; c2 < 4; ++c2)
#pragma unroll
        for (int k = 0; k < 32; ++k) {
            float v = xp[(c2 * 32 + k) * HW];
            s += v * v;
            hh[c2 * 32 + permpos32(k)] = __float2half_rn(v);
        }
    g_csum[idx] = s;
#pragma unroll
    for (int i = 0; i < 16; ++i)
        *(uint4*)&sh[tid][i * 8] = ((const uint4*)hh)[i];
    __syncthreads();

    uint4* dst = (uint4*)(g_xt + ((size_t)blockIdx.x * 128) * 128);
    for (int i = tid; i < 2048; i += 128) {
        int px = i >> 4, seg = i & 15;
        dst[i] = *(const uint4*)&sh[px][seg * 8];
    }
}

// g_wh[it][co][perm32] where it = cig*9 + pos
__global__ void wtrans_kernel(const float* __restrict__ w) {
    int idx = blockIdx.x * 256 + threadIdx.x;
    if (idx >= 9*CIN*COUT) return;
    int ci  = idx & 127;
    int r   = idx >> 7;
    int co  = r & 255;
    int pos = r >> 8;
    int it  = (ci >> 5) * 9 + pos;
    g_wh[((size_t)it*COUT + co)*32 + permpos32(ci & 31)] =
        __float2half_rn(w[((size_t)co*CIN + ci)*9 + pos]);
}

// ---------------------------------------------------------------------------
// corr_kernel: edge row-wrap correction (pre-inv), coalesced store to g_corr.
// Same half-rounded values as the main kernel (fp32 products exact).
// grid (7 oy-chunks, 8 b, 2 sides), 256 threads = one co each.
// ---------------------------------------------------------------------------
__global__ void corr_kernel() {
    const int side = blockIdx.z;
    const int b    = blockIdx.y;
    const int oc   = blockIdx.x * 16;
    const int co   = threadIdx.x;

    __shared__ __half xc[18][128];
    for (int i = threadIdx.x; i < 18 * 16; i += 256) {
        int r = i >> 4, seg = i & 15;
        int q = 0; bool v;
        if (side == 0) { int row = oc - 1 + r; v = (row >= 1 && row <= HT); q = row * WD - 1; }
        else           { int row = oc + r;     v = (row <= HT - 1);         q = row * WD;     }
        uint4 val = make_uint4(0, 0, 0, 0);
        if (v) val = *(const uint4*)(g_xt + ((size_t)b * HW + q) * 128 + seg * 8);
        *(uint4*)&xc[r][seg * 8] = val;
    }
    __syncthreads();

    const int kwsel = side ? 2 : 0;
    float corr[16];
#pragma unroll
    for (int dy = 0; dy < 16; ++dy) corr[dy] = 0.f;

#pragma unroll
    for (int kh = 0; kh < 3; ++kh) {
        const int pos = kh * 3 + kwsel;
        for (int cig = 0; cig < 4; ++cig) {
            const __half* wrow = g_wh + ((size_t)(cig * 9 + pos) * COUT + co) * 32;
#pragma unroll
            for (int c32 = 0; c32 < 32; ++c32) {
                float w = __half2float(wrow[c32]);
#pragma unroll
                for (int dy = 0; dy < 16; ++dy)
                    corr[dy] += w * __half2float(xc[dy + kh][cig * 32 + c32]);
            }
        }
    }

#pragma unroll
    for (int dy = 0; dy < 16; ++dy) {
        int oy = oc + dy;
        g_corr[(((size_t)b * HT + oy) * 2 + side) * COUT + co] = corr[dy];
    }
}

// ---------------------------------------------------------------------------
// Main conv GEMM: grid (112 rows, 2 cout-tiles, 8 batch), 256 threads,
// 2 CTAs/SM. Fully unrolled 36-tap loop; barrier every 2 taps; 4-deep A
// pipeline; double-buffered window. Computes inv-norm from g_csum inline;
// fused edge-correction subtract in the epilogue.
// ---------------------------------------------------------------------------
__global__ __launch_bounds__(256, 2)
void conv_mma_kernel(const float* __restrict__ bias, float* __restrict__ out) {
    extern __shared__ __align__(16) char dyn[];
    const uint32_t sbase = smem_u32(dyn);
    float* sInvF = (float*)(dyn + SINV_OFF);
    float* sCorr = (float*)(dyn + SCORR_OFF);   // [0..127]=left, [128..255]=right

    const int tid  = threadIdx.x;
    const int wid  = tid >> 5;
    const int lane = tid & 31;
    const int t    = lane & 3;
    const int g    = lane >> 2;
    const int m0w  = (wid & 3) * 32;
    const int n0w  = (wid >> 2) * 56;

    const int oy  = blockIdx.x;
    const int p0  = oy * NT;
    const int co0 = blockIdx.y * MT;
    const int b   = blockIdx.z;
    const __half* xtb = g_xt + (size_t)b * HW * 128;

    // inv-norm for this row, straight from csum (box-sum + rsqrt)
    if (tid < NT) {
        float s = 0.f;
#pragma unroll
        for (int dy = -1; dy <= 1; ++dy) {
            int y = oy + dy; if ((unsigned)y >= HT) continue;
#pragma unroll
            for (int dx = -1; dx <= 1; ++dx) {
                int xq = tid + dx; if ((unsigned)xq >= WD) continue;
                s += g_csum[b * HW + y * WD + xq];
            }
        }
        sInvF[tid] = 1.f / fmaxf(sqrtf(s), 1e-12f);
    }
    // edge corrections for this row / cout-tile
    {
        int side = tid >> 7;          // 0: left, 1: right
        int co   = tid & 127;
        sCorr[tid] = g_corr[(((size_t)b * HT + oy) * 2 + side) * COUT + co0 + co];
    }

    float acc[2][7][4];
#pragma unroll
    for (int mi = 0; mi < 2; ++mi)
#pragma unroll
        for (int ni = 0; ni < 7; ++ni)
#pragma unroll
            for (int q = 0; q < 4; ++q) acc[mi][ni][q] = 0.f;

    // thread-constant pieces of the fragment addresses
    const uint32_t aTh = sbase + AOFF + (uint32_t)((m0w + g) * RPB + t * 16);
    const uint32_t bTh = sbase + (uint32_t)((n0w + g) * RPB + t * 16);

    auto issueW = [&](int cig) {
        uint32_t wB = sbase + (uint32_t)(cig & 1) * WBUF;
        for (int i = tid; i < WROWS * 4; i += 256) {
            int j = i >> 2, seg = i & 3;
            int q = p0 - 113 + j;
            unsigned ok = ((unsigned)q < (unsigned)HW) ? 16u : 0u;
            int qc = q < 0 ? 0 : (q >= HW ? HW - 1 : q);
            const __half* src = xtb + (size_t)qc * 128 + cig * 32 + seg * 8;
            asm volatile("cp.async.cg.shared.global [%0], [%1], 16, %2;"
                         :: "r"(wB + (uint32_t)(j * RPB + seg * 16)), "l"(src), "r"(ok));
        }
    };
    auto issueA = [&](int it2) {
        uint32_t aB = sbase + AOFF + (uint32_t)(it2 & 3) * A_SZ;
        const __half* src = g_wh + ((size_t)it2 * COUT + co0) * 32 + (size_t)tid * 16;
        asm volatile("cp.async.cg.shared.global [%0], [%1], 16;"
                     :: "r"(aB + (uint32_t)tid * 32), "l"(src));
        asm volatile("cp.async.cg.shared.global [%0], [%1], 16;"
                     :: "r"(aB + (uint32_t)tid * 32 + 16), "l"(src + 8));
    };

    issueW(0); issueA(0); CP_COMMIT();   // G0 = {W0, A0}
    issueA(1); CP_COMMIT();              // G1 = {A1}

#pragma unroll
    for (int it = 0; it < 36; ++it) {
        const int tap = it % 9, cig = it / 9;   // compile-time after unroll

        if (it + 2 < 36) issueA(it + 2);
        if (tap == 4 && cig < 3) issueW(cig + 1);
        CP_COMMIT();                             // G(it+2)
        if ((it & 1) == 0) {
            CP_WAIT(1);                          // G0..G(it+1) complete
            __syncthreads();                     // ...and visible to all
        }

        const int dlt = (tap / 3) * WD + (tap % 3);
        const uint32_t abase = aTh + (uint32_t)(it & 3) * A_SZ;
        const uint32_t bbase = bTh + (uint32_t)((cig & 1) * WBUF + dlt * RPB);

        uint32_t a0[2][2], a1[2][2], a2[2][2], a3[2][2];  // [mi][ks]
#pragma unroll
        for (int mi = 0; mi < 2; ++mi) {
            lds128(a0[mi][0], a2[mi][0], a0[mi][1], a2[mi][1], abase + mi * 1024);
            lds128(a1[mi][0], a3[mi][0], a1[mi][1], a3[mi][1], abase + mi * 1024 + 512);
        }
#pragma unroll
        for (int ni = 0; ni < 7; ++ni) {
            uint32_t b0k0, b1k0, b0k1, b1k1;
            lds128(b0k0, b1k0, b0k1, b1k1, bbase + (uint32_t)ni * 512);
            mma16(acc[0][ni], a0[0][0], a1[0][0], a2[0][0], a3[0][0], b0k0, b1k0);
            mma16(acc[1][ni], a0[1][0], a1[1][0], a2[1][0], a3[1][0], b0k0, b1k0);
            mma16(acc[0][ni], a0[0][1], a1[0][1], a2[0][1], a3[0][1], b0k1, b1k1);
            mma16(acc[1][ni], a0[1][1], a1[1][1], a2[1][1], a3[1][1], b0k1, b1k1);
        }
    }
    __syncthreads();

    // --- epilogue: accum -> smem -> scaled, biased, edge-fixed, coalesced STG
    float* c_s = (float*)dyn;
#pragma unroll
    for (int mi = 0; mi < 2; ++mi)
#pragma unroll
        for (int ni = 0; ni < 7; ++ni) {
            const int m = m0w + mi * 16 + g;
            const int n = n0w + ni * 8 + 2 * t;
            c_s[m * PC + n]           = acc[mi][ni][0];
            c_s[m * PC + n + 1]       = acc[mi][ni][1];
            c_s[(m + 8) * PC + n]     = acc[mi][ni][2];
            c_s[(m + 8) * PC + n + 1] = acc[mi][ni][3];
        }
    __syncthreads();

    {
        const int m  = tid >> 1;
        const int cb = (tid & 1) * 56;
        const float bv = bias[co0 + m];
        float* op = out + ((size_t)b * COUT + co0 + m) * HW + p0 + cb;
#pragma unroll
        for (int j4 = 0; j4 < 14; ++j4) {
            float4 v = *(const float4*)&c_s[m * PC + cb + j4 * 4];
            float4 r;
            r.x = v.x * sInvF[cb + j4 * 4 + 0] + bv;
            r.y = v.y * sInvF[cb + j4 * 4 + 1] + bv;
            r.z = v.z * sInvF[cb + j4 * 4 + 2] + bv;
            r.w = v.w * sInvF[cb + j4 * 4 + 3] + bv;
            if (cb == 0 && j4 == 0)    r.x -= sCorr[m] * sInvF[0];          // ox=0
            if (cb == 56 && j4 == 13)  r.w -= sCorr[128 + m] * sInvF[111];  // ox=111
            *(float4*)&op[j4 * 4] = r;
        }
    }
}

// ---------------------------------------------------------------------------
extern "C" void kernel_launch(void* const* d_in, const int* in_sizes, int n_in,
                              void* d_out, int out_size) {
    const float* x    = (const float*)d_in[0];
    const float* wgt  = (const float*)d_in[1];
    const float* bias = (const float*)d_in[2];
    float* out        = (float*)d_out;

    cudaFuncSetAttribute(conv_mma_kernel,
                         cudaFuncAttributeMaxDynamicSharedMemorySize, DSMEM);

    int npix = BATCH * HW;
    prep_x<<<npix / 128, 128>>>(x);
    wtrans_kernel<<<(9 * CIN * COUT + 255) / 256, 256>>>(wgt);
    corr_kernel<<<dim3(7, 8, 2), 256>>>();

    conv_mma_kernel<<<dim3(112, 2, 8), 256, DSMEM>>>(bias, out);
}

// round 12
// speedup vs baseline: 7.8183x; 1.0043x over previous
#include <cuda_runtime.h>
#include <cuda_fp16.h>
#include <cstdint>
#include <cstddef>
#include <type_traits>

#define BATCH 8
#define CIN   128
#define HT    112
#define WD    112
#define COUT  256
#define HW    (HT*WD)

#define NT    112          // pixels per CTA (1 image row)
#define MT    128          // couts per CTA
#define WROWS 338          // staged window rows (NT + 226)
#define RPB   64           // bytes per row (32 halves, conflict-free LDS.128)
#define WBUF  (WROWS*RPB)  // 21632
#define A_SZ  (MT*RPB)     // 8192
#define AOFF  (2*WBUF)     // 43264; 4 A buffers follow -> 76032
#define PC    116          // epilogue fp32 pitch
#define SINV_OFF 76032     // 112 floats
#define SCORR_OFF 76544    // 256 floats (L then R)
#define DSMEM 77568

__device__ float g_csum[BATCH*HW];
__device__ float g_corr[BATCH*HT*2*COUT];                    // [b][oy][side][co]
__device__ __align__(256) __half g_xt[(size_t)BATCH*HW*CIN]; // [b][p][ci_perm]
__device__ __align__(256) __half g_wh[36*COUT*32];           // [it][co][32ci_perm]

// permutation within a 32-ci chunk: both 16-groups' mma fragment pairs land in
// one 16B span per thread t: halfpos = t*8 + g16*4 + inner
__device__ __host__ __forceinline__ constexpr int permpos32(int c) {
    int k = c & 15, gg = c >> 4;
    return ((k & 7) >> 1) * 8 + gg * 4 + (((k >> 3) << 1) | (k & 1));
}

// ---------------------------------------------------------------------------
__device__ __forceinline__ uint32_t smem_u32(const void* p) {
    uint32_t a;
    asm("{ .reg .u64 t; cvta.to.shared.u64 t, %1; cvt.u32.u64 %0, t; }" : "=r"(a) : "l"(p));
    return a;
}
#define CP_COMMIT() asm volatile("cp.async.commit_group;" ::: "memory")
#define CP_WAIT(n)  asm volatile("cp.async.wait_group %0;" :: "n"(n) : "memory")

// LDS.128 with compile-time immediate offset -> zero address ALU in mainloop
template <int IMM>
__device__ __forceinline__ void lds128i(uint32_t& x, uint32_t& y, uint32_t& z,
                                        uint32_t& w, uint32_t base) {
    asm volatile("ld.shared.v4.b32 {%0,%1,%2,%3}, [%4+%5];"
                 : "=r"(x), "=r"(y), "=r"(z), "=r"(w) : "r"(base), "n"(IMM));
}
__device__ __forceinline__ void mma16(float* c, uint32_t a0, uint32_t a1,
                                      uint32_t a2, uint32_t a3,
                                      uint32_t b0, uint32_t b1) {
    asm volatile(
        "mma.sync.aligned.m16n8k16.row.col.f32.f16.f16.f32 "
        "{%0,%1,%2,%3}, {%4,%5,%6,%7}, {%8,%9}, {%0,%1,%2,%3};"
        : "+f"(c[0]), "+f"(c[1]), "+f"(c[2]), "+f"(c[3])
        : "r"(a0), "r"(a1), "r"(a2), "r"(a3), "r"(b0), "r"(b1));
}

// compile-time for
template <int I, int N, typename F>
__device__ __forceinline__ void static_for(F&& f) {
    if constexpr (I < N) {
        f(std::integral_constant<int, I>{});
        static_for<I + 1, N>(f);
    }
}

// ---------------------------------------------------------------------------
// prep_x: channel sum-of-squares (fp32) + transpose to [b][p][ci_perm] half.
// 128 threads / 128 pixels per block; smem-staged fully-coalesced output.
// ---------------------------------------------------------------------------
__global__ __launch_bounds__(128)
void prep_x(const float* __restrict__ x) {
    __shared__ __half sh[128][136];     // pad 8 halves: conflict-free STS/LDS.128
    const int tid = threadIdx.x;
    const int idx = blockIdx.x * 128 + tid;     // HW % 128 == 0 -> same b per blk
    const int b = idx / HW, p = idx - b * HW;
    const float* xp = x + (size_t)b * CIN * HW + p;

    float s = 0.f;
    __half hh[128];
#pragma unroll
    for (int c2 = 0; c2 < 4; ++c2)
#pragma unroll
        for (int k = 0; k < 32; ++k) {
            float v = xp[(c2 * 32 + k) * HW];
            s += v * v;
            hh[c2 * 32 + permpos32(k)] = __float2half_rn(v);
        }
    g_csum[idx] = s;
#pragma unroll
    for (int i = 0; i < 16; ++i)
        *(uint4*)&sh[tid][i * 8] = ((const uint4*)hh)[i];
    __syncthreads();

    uint4* dst = (uint4*)(g_xt + ((size_t)blockIdx.x * 128) * 128);
    for (int i = tid; i < 2048; i += 128) {
        int px = i >> 4, seg = i & 15;
        dst[i] = *(const uint4*)&sh[px][seg * 8];
    }
}

// g_wh[it][co][perm32] where it = cig*9 + pos
__global__ void wtrans_kernel(const float* __restrict__ w) {
    int idx = blockIdx.x * 256 + threadIdx.x;
    if (idx >= 9*CIN*COUT) return;
    int ci  = idx & 127;
    int r   = idx >> 7;
    int co  = r & 255;
    int pos = r >> 8;
    int it  = (ci >> 5) * 9 + pos;
    g_wh[((size_t)it*COUT + co)*32 + permpos32(ci & 31)] =
        __float2half_rn(w[((size_t)co*CIN + ci)*9 + pos]);
}

// ---------------------------------------------------------------------------
// corr_kernel: edge row-wrap correction (pre-inv), coalesced store to g_corr.
// ---------------------------------------------------------------------------
__global__ void corr_kernel() {
    const int side = blockIdx.z;
    const int b    = blockIdx.y;
    const int oc   = blockIdx.x * 16;
    const int co   = threadIdx.x;

    __shared__ __half xc[18][128];
    for (int i = threadIdx.x; i < 18 * 16; i += 256) {
        int r = i >> 4, seg = i & 15;
        int q = 0; bool v;
        if (side == 0) { int row = oc - 1 + r; v = (row >= 1 && row <= HT); q = row * WD - 1; }
        else           { int row = oc + r;     v = (row <= HT - 1);         q = row * WD;     }
        uint4 val = make_uint4(0, 0, 0, 0);
        if (v) val = *(const uint4*)(g_xt + ((size_t)b * HW + q) * 128 + seg * 8);
        *(uint4*)&xc[r][seg * 8] = val;
    }
    __syncthreads();

    const int kwsel = side ? 2 : 0;
    float corr[16];
#pragma unroll
    for (int dy = 0; dy < 16; ++dy) corr[dy] = 0.f;

#pragma unroll
    for (int kh = 0; kh < 3; ++kh) {
        const int pos = kh * 3 + kwsel;
        for (int cig = 0; cig < 4; ++cig) {
            const __half* wrow = g_wh + ((size_t)(cig * 9 + pos) * COUT + co) * 32;
#pragma unroll
            for (int c32 = 0; c32 < 32; ++c32) {
                float w = __half2float(wrow[c32]);
#pragma unroll
                for (int dy = 0; dy < 16; ++dy)
                    corr[dy] += w * __half2float(xc[dy + kh][cig * 32 + c32]);
            }
        }
    }

#pragma unroll
    for (int dy = 0; dy < 16; ++dy) {
        int oy = oc + dy;
        g_corr[(((size_t)b * HT + oy) * 2 + side) * COUT + co] = corr[dy];
    }
}

// ---------------------------------------------------------------------------
// Main conv GEMM: grid (112 rows, 2 cout-tiles, 8 batch), 256 threads,
// 2 CTAs/SM. static_for-unrolled 36-tap loop with ALL smem offsets in LDS
// immediates (2 base regs total); barrier every 2 taps; 4-deep A pipeline;
// double-buffered window; fused inv-norm + edge-correction epilogue.
// ---------------------------------------------------------------------------
__global__ __launch_bounds__(256, 2)
void conv_mma_kernel(const float* __restrict__ bias, float* __restrict__ out) {
    extern __shared__ __align__(16) char dyn[];
    const uint32_t sbase = smem_u32(dyn);
    float* sInvF = (float*)(dyn + SINV_OFF);
    float* sCorr = (float*)(dyn + SCORR_OFF);   // [0..127]=left, [128..255]=right

    const int tid  = threadIdx.x;
    const int wid  = tid >> 5;
    const int lane = tid & 31;
    const int t    = lane & 3;
    const int g    = lane >> 2;
    const int m0w  = (wid & 3) * 32;
    const int n0w  = (wid >> 2) * 56;

    const int oy  = blockIdx.x;
    const int p0  = oy * NT;
    const int co0 = blockIdx.y * MT;
    const int b   = blockIdx.z;
    const __half* xtb = g_xt + (size_t)b * HW * 128;

    // inv-norm for this row, straight from csum (box-sum + rsqrt)
    if (tid < NT) {
        float s = 0.f;
#pragma unroll
        for (int dy = -1; dy <= 1; ++dy) {
            int y = oy + dy; if ((unsigned)y >= HT) continue;
#pragma unroll
            for (int dx = -1; dx <= 1; ++dx) {
                int xq = tid + dx; if ((unsigned)xq >= WD) continue;
                s += g_csum[b * HW + y * WD + xq];
            }
        }
        sInvF[tid] = 1.f / fmaxf(sqrtf(s), 1e-12f);
    }
    // edge corrections for this row / cout-tile
    {
        int side = tid >> 7;          // 0: left, 1: right
        int co   = tid & 127;
        sCorr[tid] = g_corr[(((size_t)b * HT + oy) * 2 + side) * COUT + co0 + co];
    }

    float acc[2][7][4];
#pragma unroll
    for (int mi = 0; mi < 2; ++mi)
#pragma unroll
        for (int ni = 0; ni < 7; ++ni)
#pragma unroll
            for (int q = 0; q < 4; ++q) acc[mi][ni][q] = 0.f;

    // thread-constant base addresses (all per-tap offsets are LDS immediates)
    const uint32_t aTh = sbase + AOFF + (uint32_t)((m0w + g) * RPB + t * 16);
    const uint32_t bTh = sbase + (uint32_t)((n0w + g) * RPB + t * 16);
    const uint32_t aDst = sbase + AOFF + (uint32_t)tid * 32;

    auto issueW = [&](int cig) {
        uint32_t wB = sbase + (uint32_t)(cig & 1) * WBUF;
        for (int i = tid; i < WROWS * 4; i += 256) {
            int j = i >> 2, seg = i & 3;
            int q = p0 - 113 + j;
            unsigned ok = ((unsigned)q < (unsigned)HW) ? 16u : 0u;
            int qc = q < 0 ? 0 : (q >= HW ? HW - 1 : q);
            const __half* src = xtb + (size_t)qc * 128 + cig * 32 + seg * 8;
            asm volatile("cp.async.cg.shared.global [%0], [%1], 16, %2;"
                         :: "r"(wB + (uint32_t)(j * RPB + seg * 16)), "l"(src), "r"(ok));
        }
    };
    auto issueA = [&](auto itc) {
        constexpr int it2 = decltype(itc)::value;
        constexpr int dimm = (it2 & 3) * A_SZ;
        const __half* src = g_wh + ((size_t)it2 * COUT + co0) * 32 + (size_t)tid * 16;
        asm volatile("cp.async.cg.shared.global [%0+%3], [%1], 16;\n\t"
                     "cp.async.cg.shared.global [%0+%4], [%2], 16;"
                     :: "r"(aDst), "l"(src), "l"(src + 8),
                        "n"(dimm), "n"(dimm + 16));
    };

    issueW(0); issueA(std::integral_constant<int, 0>{}); CP_COMMIT();
    issueA(std::integral_constant<int, 1>{}); CP_COMMIT();

    static_for<0, 36>([&](auto itc) {
        constexpr int it  = decltype(itc)::value;
        constexpr int tap = it % 9, cig = it / 9;

        if constexpr (it + 2 < 36) issueA(std::integral_constant<int, it + 2>{});
        if constexpr (tap == 4 && cig < 3) issueW(cig + 1);
        CP_COMMIT();
        if constexpr ((it & 1) == 0) {
            CP_WAIT(1);
            __syncthreads();
        }

        constexpr int dlt  = (tap / 3) * WD + (tap % 3);
        constexpr int aimm = (it & 3) * A_SZ;
        constexpr int bimm = (cig & 1) * WBUF + dlt * RPB;

        uint32_t a0[2][2], a1[2][2], a2[2][2], a3[2][2];  // [mi][ks]
        lds128i<aimm>(a0[0][0], a2[0][0], a0[0][1], a2[0][1], aTh);
        lds128i<aimm + 512>(a1[0][0], a3[0][0], a1[0][1], a3[0][1], aTh);
        lds128i<aimm + 1024>(a0[1][0], a2[1][0], a0[1][1], a2[1][1], aTh);
        lds128i<aimm + 1536>(a1[1][0], a3[1][0], a1[1][1], a3[1][1], aTh);

        static_for<0, 7>([&](auto nic) {
            constexpr int ni = decltype(nic)::value;
            uint32_t b0k0, b1k0, b0k1, b1k1;
            lds128i<bimm + ni * 512>(b0k0, b1k0, b0k1, b1k1, bTh);
            mma16(acc[0][ni], a0[0][0], a1[0][0], a2[0][0], a3[0][0], b0k0, b1k0);
            mma16(acc[1][ni], a0[1][0], a1[1][0], a2[1][0], a3[1][0], b0k0, b1k0);
            mma16(acc[0][ni], a0[0][1], a1[0][1], a2[0][1], a3[0][1], b0k1, b1k1);
            mma16(acc[1][ni], a0[1][1], a1[1][1], a2[1][1], a3[1][1], b0k1, b1k1);
        });
    });
    __syncthreads();

    // --- epilogue: accum -> smem -> scaled, biased, edge-fixed, coalesced STG
    float* c_s = (float*)dyn;
#pragma unroll
    for (int mi = 0; mi < 2; ++mi)
#pragma unroll
        for (int ni = 0; ni < 7; ++ni) {
            const int m = m0w + mi * 16 + g;
            const int n = n0w + ni * 8 + 2 * t;
            c_s[m * PC + n]           = acc[mi][ni][0];
            c_s[m * PC + n + 1]       = acc[mi][ni][1];
            c_s[(m + 8) * PC + n]     = acc[mi][ni][2];
            c_s[(m + 8) * PC + n + 1] = acc[mi][ni][3];
        }
    __syncthreads();

    {
        const int m  = tid >> 1;
        const int cb = (tid & 1) * 56;
        const float bv = bias[co0 + m];
        float* op = out + ((size_t)b * COUT + co0 + m) * HW + p0 + cb;
#pragma unroll
        for (int j4 = 0; j4 < 14; ++j4) {
            float4 v = *(const float4*)&c_s[m * PC + cb + j4 * 4];
            float4 r;
            r.x = v.x * sInvF[cb + j4 * 4 + 0] + bv;
            r.y = v.y * sInvF[cb + j4 * 4 + 1] + bv;
            r.z = v.z * sInvF[cb + j4 * 4 + 2] + bv;
            r.w = v.w * sInvF[cb + j4 * 4 + 3] + bv;
            if (cb == 0 && j4 == 0)    r.x -= sCorr[m] * sInvF[0];          // ox=0
            if (cb == 56 && j4 == 13)  r.w -= sCorr[128 + m] * sInvF[111];  // ox=111
            *(float4*)&op[j4 * 4] = r;
        }
    }
}

// ---------------------------------------------------------------------------
extern "C" void kernel_launch(void* const* d_in, const int* in_sizes, int n_in,
                              void* d_out, int out_size) {
    const float* x    = (const float*)d_in[0];
    const float* wgt  = (const float*)d_in[1];
    const float* bias = (const float*)d_in[2];
    float* out        = (float*)d_out;

    cudaFuncSetAttribute(conv_mma_kernel,
                         cudaFuncAttributeMaxDynamicSharedMemorySize, DSMEM);

    int npix = BATCH * HW;
    prep_x<<<npix / 128, 128>>>(x);
    wtrans_kernel<<<(9 * CIN * COUT + 255) / 256, 256>>>(wgt);
    corr_kernel<<<dim3(7, 8, 2), 256>>>();

    conv_mma_kernel<<<dim3(112, 2, 8), 256, DSMEM>>>(bias, out);
}